// round 1
// baseline (speedup 1.0000x reference)
#include <cuda_runtime.h>
#include <math.h>

#define NB    128     // batch
#define NT    32      // tokens
#define ND    1024    // model dim
#define NADA  1024
#define NINTER 1024
#define NRANK 8

// Scratch (allocation-free rule: __device__ globals)
__device__ float g_ae[NB * NADA];
__device__ float g_h[NB * NINTER];
__device__ float g_xw[NB * 2 * ND * NRANK];   // 8 MB
__device__ float g_P[NB * NT * NRANK];

// ---------------------------------------------------------------------------
// LayerNorm over last dim (1024), one block per row
// ---------------------------------------------------------------------------
__global__ __launch_bounds__(256) void layernorm_kernel(
    const float* __restrict__ ada, const float* __restrict__ gamma,
    const float* __restrict__ beta, float* __restrict__ out)
{
    int row = blockIdx.x;
    const float4 v = reinterpret_cast<const float4*>(ada + row * NADA)[threadIdx.x];
    float s  = v.x + v.y + v.z + v.w;
    float ss = v.x * v.x + v.y * v.y + v.z * v.z + v.w * v.w;

    __shared__ float red_s[8], red_q[8];
    #pragma unroll
    for (int o = 16; o > 0; o >>= 1) {
        s  += __shfl_xor_sync(0xFFFFFFFFu, s,  o);
        ss += __shfl_xor_sync(0xFFFFFFFFu, ss, o);
    }
    int warp = threadIdx.x >> 5, lane = threadIdx.x & 31;
    if (lane == 0) { red_s[warp] = s; red_q[warp] = ss; }
    __syncthreads();
    float sum = 0.f, sumsq = 0.f;
    #pragma unroll
    for (int i = 0; i < 8; i++) { sum += red_s[i]; sumsq += red_q[i]; }

    const float inv_n = 1.0f / NADA;
    float mu   = sum * inv_n;
    float var  = sumsq * inv_n - mu * mu;
    float rstd = rsqrtf(var + 1e-5f);

    const float4 gv = reinterpret_cast<const float4*>(gamma)[threadIdx.x];
    const float4 bv = reinterpret_cast<const float4*>(beta)[threadIdx.x];
    float4 o;
    o.x = (v.x - mu) * rstd * gv.x + bv.x;
    o.y = (v.y - mu) * rstd * gv.y + bv.y;
    o.z = (v.z - mu) * rstd * gv.z + bv.z;
    o.w = (v.w - mu) * rstd * gv.w + bv.w;
    reinterpret_cast<float4*>(out + row * NADA)[threadIdx.x] = o;
}

// ---------------------------------------------------------------------------
// P[b] = x[b] @ x_a[b] : (32x1024)@(1024x8) per sample. One block per b.
// x_a[b,d,r] = g_xw[b*16384 + d*8 + r]
// ---------------------------------------------------------------------------
__global__ __launch_bounds__(256) void p_kernel(
    const float* __restrict__ x, const float* __restrict__ xw,
    float* __restrict__ P)
{
    int b   = blockIdx.x;
    int tid = threadIdx.x;
    int t = tid >> 3, r = tid & 7;

    __shared__ float xs[NT * 128];      // 32 x 128 chunk of x
    __shared__ float as_[128 * NRANK];  // 128 x 8 chunk of x_a

    float acc = 0.f;
    for (int d0 = 0; d0 < ND; d0 += 128) {
        for (int i = tid; i < NT * 128; i += 256) {
            int rr = i >> 7, cc = i & 127;
            xs[i] = x[(b * NT + rr) * ND + d0 + cc];
        }
        for (int i = tid; i < 128 * NRANK; i += 256) {
            as_[i] = xw[b * (2 * ND * NRANK) + d0 * NRANK + i];
        }
        __syncthreads();
        #pragma unroll 8
        for (int dd = 0; dd < 128; ++dd)
            acc += xs[t * 128 + dd] * as_[dd * NRANK + r];
        __syncthreads();
    }
    P[(b * NT + t) * NRANK + r] = acc;  // == P[m*8+r] with m = b*32+t
}

// ---------------------------------------------------------------------------
// Tiled SGEMM: C = epilogue(A @ B)
// MODE 0: bias + exact GELU   (gemm1)
// MODE 1: bias                (gemm2)
// MODE 2: + residual x + P @ x_b^T  (final fused GEMM)
// Assumes M%BM==0, N%BN==0, K%BK==0, BM*BK==BK*BN==4*THREADS.
// ---------------------------------------------------------------------------
template<int BM, int BN, int BK, int TM, int TN, int MODE>
__global__ __launch_bounds__((BM/TM)*(BN/TN)) void sgemm_kernel(
    int M, int N, int K,
    const float* __restrict__ A, const float* __restrict__ Bm,
    float* __restrict__ C,
    const float* __restrict__ bias,
    const float* __restrict__ xres,
    const float* __restrict__ P,
    const float* __restrict__ xw)
{
    constexpr int TX = BN / TN;
    __shared__ float As[BK * BM];   // transposed: As[k*BM + m]
    __shared__ float Bs[BK * BN];   // Bs[k*BN + n]

    const int tid = threadIdx.x;
    const int tx = tid % TX;
    const int ty = tid / TX;
    const int m0 = blockIdx.y * BM;
    const int n0 = blockIdx.x * BN;

    const int a_r = (tid * 4) / BK, a_c = (tid * 4) % BK;
    const int b_r = (tid * 4) / BN, b_c = (tid * 4) % BN;

    float acc[TM][TN];
    #pragma unroll
    for (int i = 0; i < TM; i++)
        #pragma unroll
        for (int j = 0; j < TN; j++) acc[i][j] = 0.f;

    for (int k0 = 0; k0 < K; k0 += BK) {
        float4 av = *reinterpret_cast<const float4*>(A + (size_t)(m0 + a_r) * K + k0 + a_c);
        As[(a_c + 0) * BM + a_r] = av.x;
        As[(a_c + 1) * BM + a_r] = av.y;
        As[(a_c + 2) * BM + a_r] = av.z;
        As[(a_c + 3) * BM + a_r] = av.w;
        *reinterpret_cast<float4*>(&Bs[b_r * BN + b_c]) =
            *reinterpret_cast<const float4*>(Bm + (size_t)(k0 + b_r) * N + n0 + b_c);
        __syncthreads();

        #pragma unroll
        for (int k = 0; k < BK; k++) {
            float af[TM], bf[TN];
            #pragma unroll
            for (int i = 0; i < TM; i += 4)
                *reinterpret_cast<float4*>(&af[i]) =
                    *reinterpret_cast<const float4*>(&As[k * BM + ty * TM + i]);
            #pragma unroll
            for (int j = 0; j < TN; j += 4)
                *reinterpret_cast<float4*>(&bf[j]) =
                    *reinterpret_cast<const float4*>(&Bs[k * BN + tx * TN + j]);
            #pragma unroll
            for (int i = 0; i < TM; i++)
                #pragma unroll
                for (int j = 0; j < TN; j++)
                    acc[i][j] += af[i] * bf[j];
        }
        __syncthreads();
    }

    if (MODE == 0 || MODE == 1) {
        #pragma unroll
        for (int i = 0; i < TM; i++) {
            int m = m0 + ty * TM + i;
            #pragma unroll
            for (int j = 0; j < TN; j++) {
                int n = n0 + tx * TN + j;
                float v = acc[i][j] + bias[n];
                if (MODE == 0)
                    v = 0.5f * v * (1.0f + erff(v * 0.70710678118654752f));
                C[(size_t)m * N + n] = v;
            }
        }
    } else {
        // MODE 2: out = xres + A@B + P @ x_b^T
        // TM=8 rows of a thread lie inside one aligned 32-row group -> one b
        const int b = (m0 + ty * TM) >> 5;
        const float* xb = xw + (size_t)b * (2 * ND * NRANK) + ND * NRANK;
        float pr[TM][NRANK];
        #pragma unroll
        for (int i = 0; i < TM; i++) {
            int m = m0 + ty * TM + i;
            *reinterpret_cast<float4*>(&pr[i][0]) =
                *reinterpret_cast<const float4*>(&P[m * NRANK]);
            *reinterpret_cast<float4*>(&pr[i][4]) =
                *reinterpret_cast<const float4*>(&P[m * NRANK + 4]);
        }
        #pragma unroll
        for (int j = 0; j < TN; j++) {
            int n = n0 + tx * TN + j;
            float xbv[NRANK];
            *reinterpret_cast<float4*>(&xbv[0]) =
                *reinterpret_cast<const float4*>(&xb[n * NRANK]);
            *reinterpret_cast<float4*>(&xbv[4]) =
                *reinterpret_cast<const float4*>(&xb[n * NRANK + 4]);
            #pragma unroll
            for (int i = 0; i < TM; i++) {
                int m = m0 + ty * TM + i;
                float e = 0.f;
                #pragma unroll
                for (int r = 0; r < NRANK; r++) e += pr[i][r] * xbv[r];
                C[(size_t)m * N + n] = xres[(size_t)m * N + n] + acc[i][j] + e;
            }
        }
    }
}

// ---------------------------------------------------------------------------
extern "C" void kernel_launch(void* const* d_in, const int* in_sizes, int n_in,
                              void* d_out, int out_size)
{
    const float* x    = (const float*)d_in[0];  // (128, 32, 1024)
    const float* ada  = (const float*)d_in[1];  // (128, 1024)
    const float* base = (const float*)d_in[2];  // (1024, 1024)
    const float* w1   = (const float*)d_in[3];  // (1024, 1024)
    const float* b1   = (const float*)d_in[4];  // (1024,)
    const float* w2   = (const float*)d_in[5];  // (1024, 16384)
    const float* b2   = (const float*)d_in[6];  // (16384,)
    const float* ln_g = (const float*)d_in[7];
    const float* ln_b = (const float*)d_in[8];
    float* out = (float*)d_out;                 // (128, 32, 1024)

    float *ae, *h, *xw, *P;
    cudaGetSymbolAddress((void**)&ae, g_ae);
    cudaGetSymbolAddress((void**)&h,  g_h);
    cudaGetSymbolAddress((void**)&xw, g_xw);
    cudaGetSymbolAddress((void**)&P,  g_P);

    // 1) LayerNorm
    layernorm_kernel<<<NB, 256>>>(ada, ln_g, ln_b, ae);

    // 2) h = gelu(ae @ w1 + b1)   M=128, N=1024, K=1024
    sgemm_kernel<64, 64, 16, 4, 4, 0><<<dim3(NINTER / 64, NB / 64), 256>>>(
        NB, NINTER, NADA, ae, w1, h, b1, nullptr, nullptr, nullptr);

    // 3) xw = h @ w2 + b2         M=128, N=16384, K=1024
    sgemm_kernel<128, 128, 8, 8, 8, 1><<<dim3((2 * ND * NRANK) / 128, 1), 256>>>(
        NB, 2 * ND * NRANK, NINTER, h, w2, xw, b2, nullptr, nullptr, nullptr);

    // 4) P[b] = x[b] @ x_a[b]
    p_kernel<<<NB, 256>>>(x, xw, P);

    // 5) out = x + X @ base + P @ x_b^T   M=4096, N=1024, K=1024
    sgemm_kernel<128, 128, 8, 8, 8, 2><<<dim3(ND / 128, (NB * NT) / 128), 256>>>(
        NB * NT, ND, ND, x, base, out, nullptr, x, P, xw);
}

// round 3
// speedup vs baseline: 2.1522x; 2.1522x over previous
#include <cuda_runtime.h>
#include <cuda_bf16.h>
#include <cstdint>
#include <math.h>

#define NB     128
#define NT     32
#define ND     1024
#define NADA   1024
#define NINTER 1024
#define NRANK  8
#define GK     1024
#define BM     128
#define BN     128
#define BK     32
#define NITER  (GK / BK)          // 32
#define SROW   80                 // 64B data + 16B pad per 32-bf16 row
#define TILE_BYTES  (128 * SROW)  // 10240
#define STAGE_BYTES (4 * TILE_BYTES)
#define SMEM_SZ     (2 * STAGE_BYTES)  // 81920

// ---------------- scratch ----------------------------------------------------
__device__ __nv_bfloat16 g_x_hi[NB * NT * ND];
__device__ __nv_bfloat16 g_x_lo[NB * NT * ND];
__device__ __nv_bfloat16 g_baseT_hi[ND * ND];
__device__ __nv_bfloat16 g_baseT_lo[ND * ND];
__device__ __nv_bfloat16 g_w1T_hi[NADA * NINTER];
__device__ __nv_bfloat16 g_w1T_lo[NADA * NINTER];
__device__ __nv_bfloat16 g_w2T_hi[NINTER * 2 * ND * NRANK];
__device__ __nv_bfloat16 g_w2T_lo[NINTER * 2 * ND * NRANK];
__device__ __nv_bfloat16 g_ae_hi[NB * NADA];
__device__ __nv_bfloat16 g_ae_lo[NB * NADA];
__device__ __nv_bfloat16 g_h_hi[NB * NINTER];
__device__ __nv_bfloat16 g_h_lo[NB * NINTER];
__device__ float g_xw[NB * 2 * ND * NRANK];
__device__ float g_P[NB * NT * NRANK];

// ---------------- PTX helpers (baseline PTX only; no 'a' features) -----------
__device__ __forceinline__ uint32_t smem_u32(const void* p) {
    uint32_t a;
    asm("{ .reg .u64 t; cvta.to.shared.u64 t, %1; cvt.u32.u64 %0, t; }" : "=r"(a) : "l"(p));
    return a;
}
#define CP16(sa, ga) \
    asm volatile("cp.async.cg.shared.global [%0], [%1], 16;" :: "r"(sa), "l"(ga))
#define CP_COMMIT() asm volatile("cp.async.commit_group;")
#define CP_WAIT1()  asm volatile("cp.async.wait_group 1;")
#define CP_WAIT0()  asm volatile("cp.async.wait_group 0;")

#define LDSM4(r, addr) \
    asm volatile("ldmatrix.sync.aligned.m8n8.x4.shared.b16 {%0,%1,%2,%3}, [%4];" \
        : "=r"((r)[0]), "=r"((r)[1]), "=r"((r)[2]), "=r"((r)[3]) : "r"(addr))

#define MMA_BF16(d, a, b0, b1) \
    asm volatile("mma.sync.aligned.m16n8k16.row.col.f32.bf16.bf16.f32 " \
        "{%0,%1,%2,%3},{%4,%5,%6,%7},{%8,%9},{%0,%1,%2,%3};" \
        : "+f"((d)[0]), "+f"((d)[1]), "+f"((d)[2]), "+f"((d)[3]) \
        : "r"((a)[0]), "r"((a)[1]), "r"((a)[2]), "r"((a)[3]), "r"(b0), "r"(b1))

__device__ __forceinline__ float gelu_exact(float v) {
    return 0.5f * v * (1.0f + erff(v * 0.70710678118654752f));
}

// ---------------- conversion kernels -----------------------------------------
__global__ __launch_bounds__(256) void split_kernel(
    const float4* __restrict__ src, __nv_bfloat16* __restrict__ hi,
    __nv_bfloat16* __restrict__ lo, int n4)
{
    int i = blockIdx.x * 256 + threadIdx.x;
    if (i >= n4) return;
    float4 v = src[i];
    __nv_bfloat16 h0 = __float2bfloat16(v.x), h1 = __float2bfloat16(v.y);
    __nv_bfloat16 h2 = __float2bfloat16(v.z), h3 = __float2bfloat16(v.w);
    __nv_bfloat162* hp = reinterpret_cast<__nv_bfloat162*>(hi + (size_t)i * 4);
    __nv_bfloat162* lp = reinterpret_cast<__nv_bfloat162*>(lo + (size_t)i * 4);
    hp[0] = __halves2bfloat162(h0, h1); hp[1] = __halves2bfloat162(h2, h3);
    lp[0] = __halves2bfloat162(__float2bfloat16(v.x - __bfloat162float(h0)),
                               __float2bfloat16(v.y - __bfloat162float(h1)));
    lp[1] = __halves2bfloat162(__float2bfloat16(v.z - __bfloat162float(h2)),
                               __float2bfloat16(v.w - __bfloat162float(h3)));
}

// src [R, C] fp32 -> hiT/loT [C, R] bf16
__global__ __launch_bounds__(256) void transpose_split_kernel(
    const float* __restrict__ src, __nv_bfloat16* __restrict__ hiT,
    __nv_bfloat16* __restrict__ loT, int R, int C)
{
    __shared__ float t[32][33];
    int c0 = blockIdx.x * 32, r0 = blockIdx.y * 32;
    int x = threadIdx.x, y = threadIdx.y;
    #pragma unroll
    for (int i = 0; i < 32; i += 8)
        t[y + i][x] = src[(size_t)(r0 + y + i) * C + c0 + x];
    __syncthreads();
    #pragma unroll
    for (int i = 0; i < 32; i += 8) {
        float v = t[x][y + i];
        __nv_bfloat16 h = __float2bfloat16(v);
        size_t o = (size_t)(c0 + y + i) * R + r0 + x;
        hiT[o] = h;
        loT[o] = __float2bfloat16(v - __bfloat162float(h));
    }
}

// ---------------- layernorm (writes bf16 hi/lo) -------------------------------
__global__ __launch_bounds__(256) void layernorm_kernel(
    const float* __restrict__ ada, const float* __restrict__ gamma,
    const float* __restrict__ beta, __nv_bfloat16* __restrict__ out_hi,
    __nv_bfloat16* __restrict__ out_lo)
{
    int row = blockIdx.x;
    const float4 v = reinterpret_cast<const float4*>(ada + (size_t)row * NADA)[threadIdx.x];
    float s  = v.x + v.y + v.z + v.w;
    float ss = v.x * v.x + v.y * v.y + v.z * v.z + v.w * v.w;
    __shared__ float rs[8], rq[8];
    #pragma unroll
    for (int o = 16; o > 0; o >>= 1) {
        s  += __shfl_xor_sync(0xFFFFFFFFu, s, o);
        ss += __shfl_xor_sync(0xFFFFFFFFu, ss, o);
    }
    int warp = threadIdx.x >> 5, lane = threadIdx.x & 31;
    if (lane == 0) { rs[warp] = s; rq[warp] = ss; }
    __syncthreads();
    float sum = 0.f, sumsq = 0.f;
    #pragma unroll
    for (int i = 0; i < 8; i++) { sum += rs[i]; sumsq += rq[i]; }
    const float inv_n = 1.0f / NADA;
    float mu = sum * inv_n;
    float rstd = rsqrtf(sumsq * inv_n - mu * mu + 1e-5f);
    const float4 gv = reinterpret_cast<const float4*>(gamma)[threadIdx.x];
    const float4 bv = reinterpret_cast<const float4*>(beta)[threadIdx.x];
    float o0 = (v.x - mu) * rstd * gv.x + bv.x;
    float o1 = (v.y - mu) * rstd * gv.y + bv.y;
    float o2 = (v.z - mu) * rstd * gv.z + bv.z;
    float o3 = (v.w - mu) * rstd * gv.w + bv.w;
    __nv_bfloat16 h0 = __float2bfloat16(o0), h1 = __float2bfloat16(o1);
    __nv_bfloat16 h2 = __float2bfloat16(o2), h3 = __float2bfloat16(o3);
    size_t o = (size_t)row * NADA + threadIdx.x * 4;
    __nv_bfloat162* hp = reinterpret_cast<__nv_bfloat162*>(out_hi + o);
    __nv_bfloat162* lp = reinterpret_cast<__nv_bfloat162*>(out_lo + o);
    hp[0] = __halves2bfloat162(h0, h1); hp[1] = __halves2bfloat162(h2, h3);
    lp[0] = __halves2bfloat162(__float2bfloat16(o0 - __bfloat162float(h0)),
                               __float2bfloat16(o1 - __bfloat162float(h1)));
    lp[1] = __halves2bfloat162(__float2bfloat16(o2 - __bfloat162float(h2)),
                               __float2bfloat16(o3 - __bfloat162float(h3)));
}

// ---------------- P[b] = x[b] @ x_a[b] ----------------------------------------
__global__ __launch_bounds__(256) void p_kernel(
    const float* __restrict__ x, const float* __restrict__ xw, float* __restrict__ P)
{
    __shared__ float xa[NRANK * ND];
    int b = blockIdx.x, tid = threadIdx.x;
    const float* xwb = xw + (size_t)b * (2 * ND * NRANK);
    for (int i = tid; i < ND * NRANK; i += 256) {
        int d = i >> 3, r = i & 7;
        xa[r * ND + d] = xwb[i];
    }
    __syncthreads();
    int w = tid >> 5, lane = tid & 31;
    for (int t = w; t < NT; t += 8) {
        const float* xrow = x + ((size_t)b * NT + t) * ND;
        float acc[8] = {0, 0, 0, 0, 0, 0, 0, 0};
        for (int d0 = 0; d0 < ND; d0 += 32) {
            float xv = xrow[d0 + lane];
            #pragma unroll
            for (int r = 0; r < 8; r++) acc[r] += xv * xa[r * ND + d0 + lane];
        }
        #pragma unroll
        for (int r = 0; r < 8; r++) {
            float sv = acc[r];
            #pragma unroll
            for (int o = 16; o > 0; o >>= 1) sv += __shfl_xor_sync(0xFFFFFFFFu, sv, o);
            if (lane == r) P[((size_t)b * NT + t) * NRANK + r] = sv;
        }
    }
}

// ---------------- async tile loader: 128 rows x 32 bf16, 80B stride ----------
__device__ __forceinline__ void load_tile_async(
    uint32_t sdst, const __nv_bfloat16* __restrict__ src, int row0, int k0, int tid)
{
    #pragma unroll
    for (int i = 0; i < 2; i++) {
        int chunk = tid + i * 256;            // 0..511
        int row = chunk >> 2, c = chunk & 3;
        uint32_t sa = sdst + row * SROW + c * 16;
        const void* ga = src + (size_t)(row0 + row) * GK + k0 + c * 8;
        CP16(sa, ga);
    }
}

// ---------------- HMMA GEMM: C = 3-term-split(A @ B^T) + epilogue ------------
// MODE 0: +bias, GELU, write bf16 hi/lo
// MODE 1: +bias, write fp32
// MODE 2: + xres + P @ x_b^T, write fp32
template<int MODE>
__global__ __launch_bounds__(256, 1) void hmma_gemm_kernel(
    const __nv_bfloat16* __restrict__ Ahi, const __nv_bfloat16* __restrict__ Alo,
    const __nv_bfloat16* __restrict__ Bhi, const __nv_bfloat16* __restrict__ Blo,
    int N,
    const float* __restrict__ bias, float* __restrict__ outf,
    __nv_bfloat16* __restrict__ out_hi, __nv_bfloat16* __restrict__ out_lo,
    const float* __restrict__ xres, const float* __restrict__ P,
    const float* __restrict__ xw)
{
    extern __shared__ char smem[];
    const int tid = threadIdx.x;
    const int wid = tid >> 5, lane = tid & 31;
    const int m0 = blockIdx.y * BM;
    const int n0 = blockIdx.x * BN;
    const int wm = wid & 1;     // 0..1 over M (64 rows each)
    const int wn = wid >> 1;    // 0..3 over N (32 cols each)
    const uint32_t sbase = smem_u32(smem);

    float acc[4][4][4];
    #pragma unroll
    for (int i = 0; i < 4; i++)
        #pragma unroll
        for (int j = 0; j < 4; j++)
            #pragma unroll
            for (int e = 0; e < 4; e++) acc[i][j][e] = 0.f;

    // prologue: stages 0,1
    #pragma unroll
    for (int s = 0; s < 2; s++) {
        uint32_t st = sbase + s * STAGE_BYTES;
        load_tile_async(st + 0 * TILE_BYTES, Ahi, m0, s * BK, tid);
        load_tile_async(st + 1 * TILE_BYTES, Alo, m0, s * BK, tid);
        load_tile_async(st + 2 * TILE_BYTES, Bhi, n0, s * BK, tid);
        load_tile_async(st + 3 * TILE_BYTES, Blo, n0, s * BK, tid);
        CP_COMMIT();
    }

    // ldmatrix address components (constant per thread)
    const int a_row = wm * 64 + (lane & 15);
    const int a_off = (lane >> 4) * 16;
    const int b_row = wn * 32 + (lane & 7);
    const int b_off = (lane >> 3) * 16;

    for (int c = 0; c < NITER; ++c) {
        if (c < NITER - 1) CP_WAIT1(); else CP_WAIT0();
        __syncthreads();

        uint32_t st = sbase + (c & 1) * STAGE_BYTES;
        uint32_t sAh = st, sAl = st + TILE_BYTES;
        uint32_t sBh = st + 2 * TILE_BYTES, sBl = st + 3 * TILE_BYTES;

        // B fragments: x4 covers full BK=32 per 8-col n-tile
        uint32_t bfr[2][4][4];
        #pragma unroll
        for (int nt = 0; nt < 4; nt++) {
            uint32_t ba = (b_row + nt * 8) * SROW + b_off;
            LDSM4(bfr[0][nt], sBh + ba);
            LDSM4(bfr[1][nt], sBl + ba);
        }

        #pragma unroll
        for (int ks = 0; ks < 2; ks++) {
            uint32_t afr[2][4][4];
            #pragma unroll
            for (int mt = 0; mt < 4; mt++) {
                uint32_t aa = (a_row + mt * 16) * SROW + ks * 32 + a_off;
                LDSM4(afr[0][mt], sAh + aa);
                LDSM4(afr[1][mt], sAl + aa);
            }
            #pragma unroll
            for (int mt = 0; mt < 4; mt++)
                #pragma unroll
                for (int nt = 0; nt < 4; nt++) {
                    MMA_BF16(acc[mt][nt], afr[0][mt], bfr[0][nt][ks * 2], bfr[0][nt][ks * 2 + 1]);
                    MMA_BF16(acc[mt][nt], afr[0][mt], bfr[1][nt][ks * 2], bfr[1][nt][ks * 2 + 1]);
                    MMA_BF16(acc[mt][nt], afr[1][mt], bfr[0][nt][ks * 2], bfr[0][nt][ks * 2 + 1]);
                }
        }
        __syncthreads();
        if (c + 2 < NITER) {
            uint32_t ld = sbase + (c & 1) * STAGE_BYTES;
            int k0 = (c + 2) * BK;
            load_tile_async(ld + 0 * TILE_BYTES, Ahi, m0, k0, tid);
            load_tile_async(ld + 1 * TILE_BYTES, Alo, m0, k0, tid);
            load_tile_async(ld + 2 * TILE_BYTES, Bhi, n0, k0, tid);
            load_tile_async(ld + 3 * TILE_BYTES, Blo, n0, k0, tid);
            CP_COMMIT();
        }
    }

    // ---------------- epilogue ----------------
    if (MODE == 2) {
        // stage P rows and x_b cols in smem (reuse mainloop buffers)
        __syncthreads();
        float* Ps  = reinterpret_cast<float*>(smem);          // 128*8 = 4KB
        float* xbs = reinterpret_cast<float*>(smem + 4096);   // 4*128*8 = 16KB
        for (int i = tid; i < BM * NRANK; i += 256)
            Ps[i] = P[(size_t)m0 * NRANK + i];
        for (int i = tid; i < 4 * BN * NRANK; i += 256) {
            int g = i >> 10, j = (i >> 3) & 127, r = i & 7;
            int bg = (m0 >> 5) + g;
            xbs[i] = xw[(size_t)bg * (2 * ND * NRANK) + ND * NRANK + (size_t)(n0 + j) * NRANK + r];
        }
        __syncthreads();

        #pragma unroll
        for (int mt = 0; mt < 4; mt++) {
            int r_in0 = wm * 64 + mt * 16 + (lane >> 2);
            #pragma unroll
            for (int half = 0; half < 2; half++) {
                int r_in = r_in0 + half * 8;
                int m = m0 + r_in;
                int g = r_in >> 5;
                const float4* pr = reinterpret_cast<const float4*>(Ps + r_in * 8);
                float4 p0 = pr[0], p1 = pr[1];
                #pragma unroll
                for (int nt = 0; nt < 4; nt++) {
                    int c_in = wn * 32 + nt * 8 + (lane & 3) * 2;
                    int n = n0 + c_in;
                    const float4* xb0 = reinterpret_cast<const float4*>(xbs + (g * 128 + c_in) * 8);
                    const float4* xb1 = reinterpret_cast<const float4*>(xbs + (g * 128 + c_in + 1) * 8);
                    float4 u0 = xb0[0], u1 = xb0[1], v0 = xb1[0], v1 = xb1[1];
                    float e0 = p0.x * u0.x + p0.y * u0.y + p0.z * u0.z + p0.w * u0.w
                             + p1.x * u1.x + p1.y * u1.y + p1.z * u1.z + p1.w * u1.w;
                    float e1 = p0.x * v0.x + p0.y * v0.y + p0.z * v0.z + p0.w * v0.w
                             + p1.x * v1.x + p1.y * v1.y + p1.z * v1.z + p1.w * v1.w;
                    const float2 xr = *reinterpret_cast<const float2*>(xres + (size_t)m * N + n);
                    float2 o;
                    o.x = xr.x + acc[mt][nt][half * 2 + 0] + e0;
                    o.y = xr.y + acc[mt][nt][half * 2 + 1] + e1;
                    *reinterpret_cast<float2*>(outf + (size_t)m * N + n) = o;
                }
            }
        }
    } else {
        #pragma unroll
        for (int mt = 0; mt < 4; mt++) {
            int r_in0 = wm * 64 + mt * 16 + (lane >> 2);
            #pragma unroll
            for (int half = 0; half < 2; half++) {
                int m = m0 + r_in0 + half * 8;
                #pragma unroll
                for (int nt = 0; nt < 4; nt++) {
                    int n = n0 + wn * 32 + nt * 8 + (lane & 3) * 2;
                    float v0 = acc[mt][nt][half * 2 + 0] + bias[n];
                    float v1 = acc[mt][nt][half * 2 + 1] + bias[n + 1];
                    if (MODE == 0) {
                        float g0 = gelu_exact(v0), g1 = gelu_exact(v1);
                        __nv_bfloat16 h0 = __float2bfloat16(g0), h1 = __float2bfloat16(g1);
                        *reinterpret_cast<__nv_bfloat162*>(out_hi + (size_t)m * N + n) =
                            __halves2bfloat162(h0, h1);
                        *reinterpret_cast<__nv_bfloat162*>(out_lo + (size_t)m * N + n) =
                            __halves2bfloat162(__float2bfloat16(g0 - __bfloat162float(h0)),
                                               __float2bfloat16(g1 - __bfloat162float(h1)));
                    } else {
                        float2 o; o.x = v0; o.y = v1;
                        *reinterpret_cast<float2*>(outf + (size_t)m * N + n) = o;
                    }
                }
            }
        }
    }
}

// ---------------------------------------------------------------------------
extern "C" void kernel_launch(void* const* d_in, const int* in_sizes, int n_in,
                              void* d_out, int out_size)
{
    const float* x    = (const float*)d_in[0];
    const float* ada  = (const float*)d_in[1];
    const float* base = (const float*)d_in[2];
    const float* w1   = (const float*)d_in[3];
    const float* b1   = (const float*)d_in[4];
    const float* w2   = (const float*)d_in[5];
    const float* b2   = (const float*)d_in[6];
    const float* ln_g = (const float*)d_in[7];
    const float* ln_b = (const float*)d_in[8];
    float* out = (float*)d_out;

    __nv_bfloat16 *x_hi, *x_lo, *bT_hi, *bT_lo, *w1T_hi, *w1T_lo, *w2T_hi, *w2T_lo;
    __nv_bfloat16 *ae_hi, *ae_lo, *h_hi, *h_lo;
    float *xw, *P;
    cudaGetSymbolAddress((void**)&x_hi, g_x_hi);      cudaGetSymbolAddress((void**)&x_lo, g_x_lo);
    cudaGetSymbolAddress((void**)&bT_hi, g_baseT_hi); cudaGetSymbolAddress((void**)&bT_lo, g_baseT_lo);
    cudaGetSymbolAddress((void**)&w1T_hi, g_w1T_hi);  cudaGetSymbolAddress((void**)&w1T_lo, g_w1T_lo);
    cudaGetSymbolAddress((void**)&w2T_hi, g_w2T_hi);  cudaGetSymbolAddress((void**)&w2T_lo, g_w2T_lo);
    cudaGetSymbolAddress((void**)&ae_hi, g_ae_hi);    cudaGetSymbolAddress((void**)&ae_lo, g_ae_lo);
    cudaGetSymbolAddress((void**)&h_hi, g_h_hi);      cudaGetSymbolAddress((void**)&h_lo, g_h_lo);
    cudaGetSymbolAddress((void**)&xw, g_xw);          cudaGetSymbolAddress((void**)&P, g_P);

    cudaFuncSetAttribute(hmma_gemm_kernel<0>, cudaFuncAttributeMaxDynamicSharedMemorySize, SMEM_SZ);
    cudaFuncSetAttribute(hmma_gemm_kernel<1>, cudaFuncAttributeMaxDynamicSharedMemorySize, SMEM_SZ);
    cudaFuncSetAttribute(hmma_gemm_kernel<2>, cudaFuncAttributeMaxDynamicSharedMemorySize, SMEM_SZ);

    // input conversions
    split_kernel<<<(NB * NT * ND / 4 + 255) / 256, 256>>>(
        (const float4*)x, x_hi, x_lo, NB * NT * ND / 4);
    transpose_split_kernel<<<dim3(ND / 32, ND / 32), dim3(32, 8)>>>(base, bT_hi, bT_lo, ND, ND);
    transpose_split_kernel<<<dim3(NINTER / 32, NADA / 32), dim3(32, 8)>>>(w1, w1T_hi, w1T_lo, NADA, NINTER);
    transpose_split_kernel<<<dim3(2 * ND * NRANK / 32, NINTER / 32), dim3(32, 8)>>>(
        w2, w2T_hi, w2T_lo, NINTER, 2 * ND * NRANK);

    // hypernetwork
    layernorm_kernel<<<NB, 256>>>(ada, ln_g, ln_b, ae_hi, ae_lo);
    hmma_gemm_kernel<0><<<dim3(NINTER / BN, 1), 256, SMEM_SZ>>>(
        ae_hi, ae_lo, w1T_hi, w1T_lo, NINTER, b1, nullptr, h_hi, h_lo, nullptr, nullptr, nullptr);
    hmma_gemm_kernel<1><<<dim3(2 * ND * NRANK / BN, 1), 256, SMEM_SZ>>>(
        h_hi, h_lo, w2T_hi, w2T_lo, 2 * ND * NRANK, b2, xw, nullptr, nullptr, nullptr, nullptr, nullptr);

    // low-rank path + fused final GEMM
    p_kernel<<<NB, 256>>>(x, xw, P);
    hmma_gemm_kernel<2><<<dim3(ND / BN, NB * NT / BM), 256, SMEM_SZ>>>(
        x_hi, x_lo, bT_hi, bT_lo, ND, nullptr, out, nullptr, nullptr, x, P, xw);
}

// round 4
// speedup vs baseline: 3.8111x; 1.7708x over previous
#include <cuda_runtime.h>
#include <cuda_fp16.h>
#include <cstdint>
#include <math.h>

#define NB     128
#define NT     32
#define ND     1024
#define NADA   1024
#define NINTER 1024
#define NRANK  8
#define GK     1024
#define BM     128
#define BN     128
#define BK     32
#define NITER  (GK / BK)     // 32
#define SRA    80            // A row: 32 halves (64B) + 16B pad
#define SRB    272           // B row: 128 halves (256B) + 16B pad
#define ATILE  (128 * SRA)   // 10240
#define BTILE  (32 * SRB)    // 8704

// ---------------- scratch ----------------------------------------------------
__device__ __half g_ae[NB * NADA];
__device__ __half g_h[NB * NINTER];
__device__ float  g_xw[NB * 2 * ND * NRANK];
__device__ float  g_P[NB * NT * NRANK];

// ---------------- PTX helpers -------------------------------------------------
__device__ __forceinline__ uint32_t smem_u32(const void* p) {
    uint32_t a;
    asm("{ .reg .u64 t; cvta.to.shared.u64 t, %1; cvt.u32.u64 %0, t; }" : "=r"(a) : "l"(p));
    return a;
}
#define LDSM4(r, addr) \
    asm volatile("ldmatrix.sync.aligned.m8n8.x4.shared.b16 {%0,%1,%2,%3}, [%4];" \
        : "=r"((r)[0]), "=r"((r)[1]), "=r"((r)[2]), "=r"((r)[3]) : "r"(addr))
#define LDSM4T(r, addr) \
    asm volatile("ldmatrix.sync.aligned.m8n8.x4.trans.shared.b16 {%0,%1,%2,%3}, [%4];" \
        : "=r"((r)[0]), "=r"((r)[1]), "=r"((r)[2]), "=r"((r)[3]) : "r"(addr))
#define MMA_F16(d, a, b0, b1) \
    asm volatile("mma.sync.aligned.m16n8k16.row.col.f32.f16.f16.f32 " \
        "{%0,%1,%2,%3},{%4,%5,%6,%7},{%8,%9},{%0,%1,%2,%3};" \
        : "+f"((d)[0]), "+f"((d)[1]), "+f"((d)[2]), "+f"((d)[3]) \
        : "r"((a)[0]), "r"((a)[1]), "r"((a)[2]), "r"((a)[3]), "r"(b0), "r"(b1))

__device__ __forceinline__ float gelu_exact(float v) {
    return 0.5f * v * (1.0f + erff(v * 0.70710678118654752f));
}

// ---------------- layernorm (writes fp16) -------------------------------------
__global__ __launch_bounds__(256) void layernorm_kernel(
    const float* __restrict__ ada, const float* __restrict__ gamma,
    const float* __restrict__ beta, __half* __restrict__ outh)
{
    int row = blockIdx.x;
    const float4 v = reinterpret_cast<const float4*>(ada + (size_t)row * NADA)[threadIdx.x];
    float s  = v.x + v.y + v.z + v.w;
    float ss = v.x * v.x + v.y * v.y + v.z * v.z + v.w * v.w;
    __shared__ float rs[8], rq[8];
    #pragma unroll
    for (int o = 16; o > 0; o >>= 1) {
        s  += __shfl_xor_sync(0xFFFFFFFFu, s, o);
        ss += __shfl_xor_sync(0xFFFFFFFFu, ss, o);
    }
    int warp = threadIdx.x >> 5, lane = threadIdx.x & 31;
    if (lane == 0) { rs[warp] = s; rq[warp] = ss; }
    __syncthreads();
    float sum = 0.f, sumsq = 0.f;
    #pragma unroll
    for (int i = 0; i < 8; i++) { sum += rs[i]; sumsq += rq[i]; }
    const float inv_n = 1.0f / NADA;
    float mu = sum * inv_n;
    float rstd = rsqrtf(sumsq * inv_n - mu * mu + 1e-5f);
    const float4 gv = reinterpret_cast<const float4*>(gamma)[threadIdx.x];
    const float4 bv = reinterpret_cast<const float4*>(beta)[threadIdx.x];
    float o0 = (v.x - mu) * rstd * gv.x + bv.x;
    float o1 = (v.y - mu) * rstd * gv.y + bv.y;
    float o2 = (v.z - mu) * rstd * gv.z + bv.z;
    float o3 = (v.w - mu) * rstd * gv.w + bv.w;
    __half2 hh[2] = { __floats2half2_rn(o0, o1), __floats2half2_rn(o2, o3) };
    *reinterpret_cast<uint2*>(outh + (size_t)row * NADA + threadIdx.x * 4) =
        *reinterpret_cast<uint2*>(hh);
}

// ---------------- P[b] = x[b] @ x_a[b] ----------------------------------------
__global__ __launch_bounds__(256) void p_kernel(
    const float* __restrict__ x, const float* __restrict__ xw, float* __restrict__ P)
{
    __shared__ float xa[NRANK * ND];
    int b = blockIdx.x, tid = threadIdx.x;
    const float* xwb = xw + (size_t)b * (2 * ND * NRANK);
    for (int i = tid; i < ND * NRANK; i += 256) {
        int d = i >> 3, r = i & 7;
        xa[r * ND + d] = xwb[i];
    }
    __syncthreads();
    int w = tid >> 5, lane = tid & 31;
    for (int t = w; t < NT; t += 8) {
        const float* xrow = x + ((size_t)b * NT + t) * ND;
        float acc[8] = {0, 0, 0, 0, 0, 0, 0, 0};
        for (int d0 = 0; d0 < ND; d0 += 32) {
            float xv = xrow[d0 + lane];
            #pragma unroll
            for (int r = 0; r < 8; r++) acc[r] += xv * xa[r * ND + d0 + lane];
        }
        #pragma unroll
        for (int r = 0; r < 8; r++) {
            float sv = acc[r];
            #pragma unroll
            for (int o = 16; o > 0; o >>= 1) sv += __shfl_xor_sync(0xFFFFFFFFu, sv, o);
            if (lane == r) P[((size_t)b * NT + t) * NRANK + r] = sv;
        }
    }
}

// ---------------- fp16 HMMA GEMM, inline fp32->fp16 conversion ----------------
// MODE 0: A fp16, B fp32->fp16;            epi: +bias, GELU -> fp16
// MODE 1: A fp16, B fp32->fp16;            epi: +bias -> fp32
// MODE 2: A fp32->hi/lo fp16 (2 terms), B fp32->fp16; epi: +xres + P@x_b^T -> fp32
template<int MODE>
__global__ __launch_bounds__(256) void gemm_kernel(
    const void* __restrict__ Aptr, const float* __restrict__ B, int N,
    const float* __restrict__ bias, float* __restrict__ outf,
    __half* __restrict__ outh,
    const float* __restrict__ xres, const float* __restrict__ P,
    const float* __restrict__ xw)
{
    extern __shared__ char smem[];
    constexpr int TERMS = (MODE == 2) ? 2 : 1;
    constexpr int STAGE = TERMS * ATILE + BTILE;
    const int tid = threadIdx.x, wid = tid >> 5, lane = tid & 31;
    const int m0 = blockIdx.y * BM, n0 = blockIdx.x * BN;
    const int wm = wid & 1, wn = wid >> 1;
    const uint32_t sb = smem_u32(smem);

    float acc[4][4][4];
    #pragma unroll
    for (int i = 0; i < 4; i++)
        #pragma unroll
        for (int j = 0; j < 4; j++)
            #pragma unroll
            for (int e = 0; e < 4; e++) acc[i][j][e] = 0.f;

    uint4  ra16[2];
    float4 ra32[4];
    float4 rb[4];

    auto loadA = [&](int k0) {
        if (MODE == 2) {
            const float* A = (const float*)Aptr;
            #pragma unroll
            for (int i = 0; i < 4; i++) {
                int ch = tid + i * 256, r = ch >> 3, c = ch & 7;
                ra32[i] = *reinterpret_cast<const float4*>(A + (size_t)(m0 + r) * GK + k0 + c * 4);
            }
        } else {
            const __half* A = (const __half*)Aptr;
            #pragma unroll
            for (int i = 0; i < 2; i++) {
                int ch = tid + i * 256, r = ch >> 2, c = ch & 3;
                ra16[i] = *reinterpret_cast<const uint4*>(A + (size_t)(m0 + r) * GK + k0 + c * 8);
            }
        }
    };
    auto loadB = [&](int k0) {
        #pragma unroll
        for (int i = 0; i < 4; i++) {
            int ch = tid + i * 256, r = ch >> 5, c = ch & 31;
            rb[i] = *reinterpret_cast<const float4*>(B + (size_t)(k0 + r) * N + n0 + c * 4);
        }
    };
    auto storeA = [&](int s) {
        char* stg = smem + s * STAGE;
        if (MODE == 2) {
            #pragma unroll
            for (int i = 0; i < 4; i++) {
                int ch = tid + i * 256, r = ch >> 3, c = ch & 7;
                float4 v = ra32[i];
                __half2 h01 = __floats2half2_rn(v.x, v.y);
                __half2 h23 = __floats2half2_rn(v.z, v.w);
                __half2 hh[2] = { h01, h23 };
                *reinterpret_cast<uint2*>(stg + r * SRA + c * 8) = *reinterpret_cast<uint2*>(hh);
                __half2 ll[2] = {
                    __floats2half2_rn(v.x - __low2float(h01), v.y - __high2float(h01)),
                    __floats2half2_rn(v.z - __low2float(h23), v.w - __high2float(h23)) };
                *reinterpret_cast<uint2*>(stg + ATILE + r * SRA + c * 8) = *reinterpret_cast<uint2*>(ll);
            }
        } else {
            #pragma unroll
            for (int i = 0; i < 2; i++) {
                int ch = tid + i * 256, r = ch >> 2, c = ch & 3;
                *reinterpret_cast<uint4*>(stg + r * SRA + c * 16) = ra16[i];
            }
        }
    };
    auto storeB = [&](int s) {
        char* stg = smem + s * STAGE + TERMS * ATILE;
        #pragma unroll
        for (int i = 0; i < 4; i++) {
            int ch = tid + i * 256, r = ch >> 5, c = ch & 31;
            float4 v = rb[i];
            __half2 hh[2] = { __floats2half2_rn(v.x, v.y), __floats2half2_rn(v.z, v.w) };
            *reinterpret_cast<uint2*>(stg + r * SRB + c * 8) = *reinterpret_cast<uint2*>(hh);
        }
    };

    const int a_row  = wm * 64 + (lane & 15);
    const int a_off  = (lane >> 4) * 16;
    const int b_row  = lane & 15;
    const int b_colb = wn * 64 + (lane >> 4) * 16;   // bytes

    auto compute = [&](int s) {
        uint32_t base = sb + s * STAGE;
        #pragma unroll
        for (int ks = 0; ks < 2; ks++) {
            uint32_t af[TERMS][4][4];
            #pragma unroll
            for (int t = 0; t < TERMS; t++)
                #pragma unroll
                for (int mt = 0; mt < 4; mt++)
                    LDSM4(af[t][mt], base + t * ATILE + (a_row + mt * 16) * SRA + ks * 32 + a_off);
            uint32_t bf[4][2];
            #pragma unroll
            for (int pr = 0; pr < 2; pr++) {
                uint32_t r[4];
                LDSM4T(r, base + TERMS * ATILE + (ks * 16 + b_row) * SRB + b_colb + pr * 32);
                bf[pr * 2 + 0][0] = r[0]; bf[pr * 2 + 0][1] = r[1];
                bf[pr * 2 + 1][0] = r[2]; bf[pr * 2 + 1][1] = r[3];
            }
            #pragma unroll
            for (int mt = 0; mt < 4; mt++)
                #pragma unroll
                for (int nt = 0; nt < 4; nt++) {
                    MMA_F16(acc[mt][nt], af[0][mt], bf[nt][0], bf[nt][1]);
                    if (TERMS == 2)
                        MMA_F16(acc[mt][nt], af[1][mt], bf[nt][0], bf[nt][1]);
                }
        }
    };

    // prologue
    loadA(0); loadB(0);
    storeA(0); storeB(0);
    loadA(BK); loadB(BK);
    __syncthreads();

    for (int c = 0; c < NITER; c++) {
        compute(c & 1);
        if (c + 1 < NITER) { storeA((c + 1) & 1); storeB((c + 1) & 1); }
        if (c + 2 < NITER) { loadA((c + 2) * BK); loadB((c + 2) * BK); }
        __syncthreads();
    }

    // ---------------- epilogue ----------------
    if (MODE == 2) {
        float* Ps  = reinterpret_cast<float*>(smem);          // 4 KB
        float* xbs = reinterpret_cast<float*>(smem + 4096);   // 16 KB
        for (int i = tid; i < BM * NRANK; i += 256)
            Ps[i] = P[(size_t)m0 * NRANK + i];
        for (int i = tid; i < 4 * BN * NRANK; i += 256) {
            int g = i >> 10, j = (i >> 3) & 127, r = i & 7;
            int bg = (m0 >> 5) + g;
            xbs[i] = xw[(size_t)bg * (2 * ND * NRANK) + ND * NRANK + (size_t)(n0 + j) * NRANK + r];
        }
        __syncthreads();

        #pragma unroll
        for (int mt = 0; mt < 4; mt++) {
            int r_in0 = wm * 64 + mt * 16 + (lane >> 2);
            #pragma unroll
            for (int half = 0; half < 2; half++) {
                int r_in = r_in0 + half * 8;
                int m = m0 + r_in;
                int g = r_in >> 5;
                const float4* pr = reinterpret_cast<const float4*>(Ps + r_in * 8);
                float4 p0 = pr[0], p1 = pr[1];
                #pragma unroll
                for (int nt = 0; nt < 4; nt++) {
                    int c_in = wn * 32 + nt * 8 + (lane & 3) * 2;
                    int n = n0 + c_in;
                    const float4* xb0 = reinterpret_cast<const float4*>(xbs + (g * 128 + c_in) * 8);
                    const float4* xb1 = reinterpret_cast<const float4*>(xbs + (g * 128 + c_in + 1) * 8);
                    float4 u0 = xb0[0], u1 = xb0[1], v0 = xb1[0], v1 = xb1[1];
                    float e0 = p0.x * u0.x + p0.y * u0.y + p0.z * u0.z + p0.w * u0.w
                             + p1.x * u1.x + p1.y * u1.y + p1.z * u1.z + p1.w * u1.w;
                    float e1 = p0.x * v0.x + p0.y * v0.y + p0.z * v0.z + p0.w * v0.w
                             + p1.x * v1.x + p1.y * v1.y + p1.z * v1.z + p1.w * v1.w;
                    const float2 xr = *reinterpret_cast<const float2*>(xres + (size_t)m * N + n);
                    float2 o;
                    o.x = xr.x + acc[mt][nt][half * 2 + 0] + e0;
                    o.y = xr.y + acc[mt][nt][half * 2 + 1] + e1;
                    *reinterpret_cast<float2*>(outf + (size_t)m * N + n) = o;
                }
            }
        }
    } else {
        #pragma unroll
        for (int mt = 0; mt < 4; mt++) {
            int r_in0 = wm * 64 + mt * 16 + (lane >> 2);
            #pragma unroll
            for (int half = 0; half < 2; half++) {
                int m = m0 + r_in0 + half * 8;
                #pragma unroll
                for (int nt = 0; nt < 4; nt++) {
                    int n = n0 + wn * 32 + nt * 8 + (lane & 3) * 2;
                    float v0 = acc[mt][nt][half * 2 + 0] + bias[n];
                    float v1 = acc[mt][nt][half * 2 + 1] + bias[n + 1];
                    if (MODE == 0) {
                        *reinterpret_cast<__half2*>(outh + (size_t)m * N + n) =
                            __floats2half2_rn(gelu_exact(v0), gelu_exact(v1));
                    } else {
                        float2 o; o.x = v0; o.y = v1;
                        *reinterpret_cast<float2*>(outf + (size_t)m * N + n) = o;
                    }
                }
            }
        }
    }
}

// ---------------------------------------------------------------------------
#define SMEM01 (2 * (ATILE + BTILE))          // 37888
#define SMEM2  (2 * (2 * ATILE + BTILE))      // 58368

extern "C" void kernel_launch(void* const* d_in, const int* in_sizes, int n_in,
                              void* d_out, int out_size)
{
    const float* x    = (const float*)d_in[0];
    const float* ada  = (const float*)d_in[1];
    const float* base = (const float*)d_in[2];
    const float* w1   = (const float*)d_in[3];
    const float* b1   = (const float*)d_in[4];
    const float* w2   = (const float*)d_in[5];
    const float* b2   = (const float*)d_in[6];
    const float* ln_g = (const float*)d_in[7];
    const float* ln_b = (const float*)d_in[8];
    float* out = (float*)d_out;

    __half *ae, *h;
    float *xw, *P;
    cudaGetSymbolAddress((void**)&ae, g_ae);
    cudaGetSymbolAddress((void**)&h,  g_h);
    cudaGetSymbolAddress((void**)&xw, g_xw);
    cudaGetSymbolAddress((void**)&P,  g_P);

    cudaFuncSetAttribute(gemm_kernel<0>, cudaFuncAttributeMaxDynamicSharedMemorySize, SMEM01);
    cudaFuncSetAttribute(gemm_kernel<1>, cudaFuncAttributeMaxDynamicSharedMemorySize, SMEM01);
    cudaFuncSetAttribute(gemm_kernel<2>, cudaFuncAttributeMaxDynamicSharedMemorySize, SMEM2);

    layernorm_kernel<<<NB, 256>>>(ada, ln_g, ln_b, ae);
    gemm_kernel<0><<<dim3(NINTER / BN, 1), 256, SMEM01>>>(
        ae, w1, NINTER, b1, nullptr, h, nullptr, nullptr, nullptr);
    gemm_kernel<1><<<dim3(2 * ND * NRANK / BN, 1), 256, SMEM01>>>(
        h, w2, 2 * ND * NRANK, b2, xw, nullptr, nullptr, nullptr, nullptr);
    p_kernel<<<NB, 256>>>(x, xw, P);
    gemm_kernel<2><<<dim3(ND / BN, NB * NT / BM), 256, SMEM2>>>(
        x, base, ND, nullptr, out, nullptr, x, P, xw);
}

// round 5
// speedup vs baseline: 4.3654x; 1.1454x over previous
#include <cuda_runtime.h>
#include <cuda_fp16.h>
#include <cstdint>
#include <math.h>

#define NB     128
#define NT     32
#define ND     1024
#define NADA   1024
#define NINTER 1024
#define NRANK  8
#define GK     1024
#define BM     128
#define BN     128
#define BK     32
#define NITER  (GK / BK)     // 32
#define SRA    80            // A row: 32 halves (64B) + 16B pad
#define SRB    272           // B row: 128 halves (256B) + 16B pad
#define ATILE  (128 * SRA)   // 10240
#define BTILE  (32 * SRB)    // 8704
#define PCHUNKS 8
#define PSZ    (NB * NT * NRANK)   // 32768

// ---------------- scratch ----------------------------------------------------
__device__ __half g_ae[NB * NADA];
__device__ __half g_h[NB * NINTER];
__device__ float  g_xw[NB * 2 * ND * NRANK];
__device__ float  g_Ppart[PCHUNKS * PSZ];

// ---------------- PTX helpers -------------------------------------------------
__device__ __forceinline__ uint32_t smem_u32(const void* p) {
    uint32_t a;
    asm("{ .reg .u64 t; cvta.to.shared.u64 t, %1; cvt.u32.u64 %0, t; }" : "=r"(a) : "l"(p));
    return a;
}
#define LDSM4(r, addr) \
    asm volatile("ldmatrix.sync.aligned.m8n8.x4.shared.b16 {%0,%1,%2,%3}, [%4];" \
        : "=r"((r)[0]), "=r"((r)[1]), "=r"((r)[2]), "=r"((r)[3]) : "r"(addr))
#define LDSM4T(r, addr) \
    asm volatile("ldmatrix.sync.aligned.m8n8.x4.trans.shared.b16 {%0,%1,%2,%3}, [%4];" \
        : "=r"((r)[0]), "=r"((r)[1]), "=r"((r)[2]), "=r"((r)[3]) : "r"(addr))
#define MMA_F16(d, a, b0, b1) \
    asm volatile("mma.sync.aligned.m16n8k16.row.col.f32.f16.f16.f32 " \
        "{%0,%1,%2,%3},{%4,%5,%6,%7},{%8,%9},{%0,%1,%2,%3};" \
        : "+f"((d)[0]), "+f"((d)[1]), "+f"((d)[2]), "+f"((d)[3]) \
        : "r"((a)[0]), "r"((a)[1]), "r"((a)[2]), "r"((a)[3]), "r"(b0), "r"(b1))

__device__ __forceinline__ float gelu_exact(float v) {
    return 0.5f * v * (1.0f + erff(v * 0.70710678118654752f));
}

// ---------------- layernorm (writes fp16) -------------------------------------
__global__ __launch_bounds__(256) void layernorm_kernel(
    const float* __restrict__ ada, const float* __restrict__ gamma,
    const float* __restrict__ beta, __half* __restrict__ outh)
{
    int row = blockIdx.x;
    const float4 v = reinterpret_cast<const float4*>(ada + (size_t)row * NADA)[threadIdx.x];
    float s  = v.x + v.y + v.z + v.w;
    float ss = v.x * v.x + v.y * v.y + v.z * v.z + v.w * v.w;
    __shared__ float rs[8], rq[8];
    #pragma unroll
    for (int o = 16; o > 0; o >>= 1) {
        s  += __shfl_xor_sync(0xFFFFFFFFu, s, o);
        ss += __shfl_xor_sync(0xFFFFFFFFu, ss, o);
    }
    int warp = threadIdx.x >> 5, lane = threadIdx.x & 31;
    if (lane == 0) { rs[warp] = s; rq[warp] = ss; }
    __syncthreads();
    float sum = 0.f, sumsq = 0.f;
    #pragma unroll
    for (int i = 0; i < 8; i++) { sum += rs[i]; sumsq += rq[i]; }
    const float inv_n = 1.0f / NADA;
    float mu = sum * inv_n;
    float rstd = rsqrtf(sumsq * inv_n - mu * mu + 1e-5f);
    const float4 gv = reinterpret_cast<const float4*>(gamma)[threadIdx.x];
    const float4 bv = reinterpret_cast<const float4*>(beta)[threadIdx.x];
    float o0 = (v.x - mu) * rstd * gv.x + bv.x;
    float o1 = (v.y - mu) * rstd * gv.y + bv.y;
    float o2 = (v.z - mu) * rstd * gv.z + bv.z;
    float o3 = (v.w - mu) * rstd * gv.w + bv.w;
    __half2 hh[2] = { __floats2half2_rn(o0, o1), __floats2half2_rn(o2, o3) };
    *reinterpret_cast<uint2*>(outh + (size_t)row * NADA + threadIdx.x * 4) =
        *reinterpret_cast<uint2*>(hh);
}

// ---------------- partial P: grid (b, chunk), chunk covers 128 d-values -------
__global__ __launch_bounds__(256) void p_partial_kernel(
    const float* __restrict__ x, const float* __restrict__ xw, float* __restrict__ Pp)
{
    __shared__ float xa[NRANK * 128];   // [r][d]
    int b = blockIdx.x, c = blockIdx.y, tid = threadIdx.x;
    const float* xwb = xw + (size_t)b * (2 * ND * NRANK) + c * 128 * NRANK;
    for (int i = tid; i < 128 * NRANK; i += 256) {
        int d = i >> 3, r = i & 7;
        xa[r * 128 + d] = xwb[i];
    }
    __syncthreads();
    int w = tid >> 5, lane = tid & 31;
    for (int t = w; t < NT; t += 8) {
        const float* xrow = x + ((size_t)b * NT + t) * ND + c * 128;
        float acc[8] = {0, 0, 0, 0, 0, 0, 0, 0};
        #pragma unroll
        for (int d0 = 0; d0 < 128; d0 += 32) {
            float xv = xrow[d0 + lane];
            #pragma unroll
            for (int r = 0; r < 8; r++) acc[r] += xv * xa[r * 128 + d0 + lane];
        }
        #pragma unroll
        for (int r = 0; r < 8; r++) {
            float sv = acc[r];
            #pragma unroll
            for (int o = 16; o > 0; o >>= 1) sv += __shfl_xor_sync(0xFFFFFFFFu, sv, o);
            if (lane == r) Pp[(size_t)c * PSZ + ((size_t)b * NT + t) * NRANK + r] = sv;
        }
    }
}

// ---------------- fp16 HMMA GEMM, inline fp32->fp16 conversion ----------------
// MODE 0: A fp16, B fp32->fp16;  epi: +bias, GELU -> fp16
// MODE 1: A fp16, B fp32->fp16;  epi: +bias -> fp32
// MODE 2: A fp32->fp16, B fp32->fp16; epi: +xres + P@x_b^T -> fp32
template<int MODE>
__global__ __launch_bounds__(256) void gemm_kernel(
    const void* __restrict__ Aptr, const float* __restrict__ B, int N,
    const float* __restrict__ bias, float* __restrict__ outf,
    __half* __restrict__ outh,
    const float* __restrict__ xres, const float* __restrict__ Pp,
    const float* __restrict__ xw)
{
    extern __shared__ char smem[];
    constexpr int STAGE = ATILE + BTILE;
    const int tid = threadIdx.x, wid = tid >> 5, lane = tid & 31;
    const int m0 = blockIdx.y * BM, n0 = blockIdx.x * BN;
    const int wm = wid & 1, wn = wid >> 1;
    const uint32_t sb = smem_u32(smem);

    float acc[4][4][4];
    #pragma unroll
    for (int i = 0; i < 4; i++)
        #pragma unroll
        for (int j = 0; j < 4; j++)
            #pragma unroll
            for (int e = 0; e < 4; e++) acc[i][j][e] = 0.f;

    uint4  ra16[2];
    float4 ra32[4];
    float4 rb[4];

    auto loadA = [&](int k0) {
        if (MODE == 2) {
            const float* A = (const float*)Aptr;
            #pragma unroll
            for (int i = 0; i < 4; i++) {
                int ch = tid + i * 256, r = ch >> 3, c = ch & 7;
                ra32[i] = *reinterpret_cast<const float4*>(A + (size_t)(m0 + r) * GK + k0 + c * 4);
            }
        } else {
            const __half* A = (const __half*)Aptr;
            #pragma unroll
            for (int i = 0; i < 2; i++) {
                int ch = tid + i * 256, r = ch >> 2, c = ch & 3;
                ra16[i] = *reinterpret_cast<const uint4*>(A + (size_t)(m0 + r) * GK + k0 + c * 8);
            }
        }
    };
    auto loadB = [&](int k0) {
        #pragma unroll
        for (int i = 0; i < 4; i++) {
            int ch = tid + i * 256, r = ch >> 5, c = ch & 31;
            rb[i] = *reinterpret_cast<const float4*>(B + (size_t)(k0 + r) * N + n0 + c * 4);
        }
    };
    auto storeA = [&](int s) {
        char* stg = smem + s * STAGE;
        if (MODE == 2) {
            #pragma unroll
            for (int i = 0; i < 4; i++) {
                int ch = tid + i * 256, r = ch >> 3, c = ch & 7;
                float4 v = ra32[i];
                __half2 hh[2] = { __floats2half2_rn(v.x, v.y), __floats2half2_rn(v.z, v.w) };
                *reinterpret_cast<uint2*>(stg + r * SRA + c * 8) = *reinterpret_cast<uint2*>(hh);
            }
        } else {
            #pragma unroll
            for (int i = 0; i < 2; i++) {
                int ch = tid + i * 256, r = ch >> 2, c = ch & 3;
                *reinterpret_cast<uint4*>(stg + r * SRA + c * 16) = ra16[i];
            }
        }
    };
    auto storeB = [&](int s) {
        char* stg = smem + s * STAGE + ATILE;
        #pragma unroll
        for (int i = 0; i < 4; i++) {
            int ch = tid + i * 256, r = ch >> 5, c = ch & 31;
            float4 v = rb[i];
            __half2 hh[2] = { __floats2half2_rn(v.x, v.y), __floats2half2_rn(v.z, v.w) };
            *reinterpret_cast<uint2*>(stg + r * SRB + c * 8) = *reinterpret_cast<uint2*>(hh);
        }
    };

    const int a_row  = wm * 64 + (lane & 15);
    const int a_off  = (lane >> 4) * 16;
    const int b_row  = lane & 15;
    const int b_colb = wn * 64 + (lane >> 4) * 16;   // bytes

    auto compute = [&](int s) {
        uint32_t base = sb + s * STAGE;
        #pragma unroll
        for (int ks = 0; ks < 2; ks++) {
            uint32_t af[4][4];
            #pragma unroll
            for (int mt = 0; mt < 4; mt++)
                LDSM4(af[mt], base + (a_row + mt * 16) * SRA + ks * 32 + a_off);
            uint32_t bf[4][2];
            #pragma unroll
            for (int pr = 0; pr < 2; pr++) {
                uint32_t r[4];
                LDSM4T(r, base + ATILE + (ks * 16 + b_row) * SRB + b_colb + pr * 32);
                bf[pr * 2 + 0][0] = r[0]; bf[pr * 2 + 0][1] = r[1];
                bf[pr * 2 + 1][0] = r[2]; bf[pr * 2 + 1][1] = r[3];
            }
            #pragma unroll
            for (int mt = 0; mt < 4; mt++)
                #pragma unroll
                for (int nt = 0; nt < 4; nt++)
                    MMA_F16(acc[mt][nt], af[mt], bf[nt][0], bf[nt][1]);
        }
    };

    // prologue
    loadA(0); loadB(0);
    storeA(0); storeB(0);
    loadA(BK); loadB(BK);
    __syncthreads();

    for (int c = 0; c < NITER; c++) {
        compute(c & 1);
        if (c + 1 < NITER) { storeA((c + 1) & 1); storeB((c + 1) & 1); }
        if (c + 2 < NITER) { loadA((c + 2) * BK); loadB((c + 2) * BK); }
        __syncthreads();
    }

    // ---------------- epilogue ----------------
    if (MODE == 2) {
        float* Ps  = reinterpret_cast<float*>(smem);          // 4 KB
        float* xbs = reinterpret_cast<float*>(smem + 4096);   // 16 KB
        for (int i = tid; i < BM * NRANK; i += 256) {
            float sv = 0.f;
            #pragma unroll
            for (int c = 0; c < PCHUNKS; c++)
                sv += Pp[(size_t)c * PSZ + (size_t)m0 * NRANK + i];
            Ps[i] = sv;
        }
        for (int i = tid; i < 4 * BN * NRANK; i += 256) {
            int g = i >> 10, j = (i >> 3) & 127, r = i & 7;
            int bg = (m0 >> 5) + g;
            xbs[i] = xw[(size_t)bg * (2 * ND * NRANK) + ND * NRANK + (size_t)(n0 + j) * NRANK + r];
        }
        __syncthreads();

        #pragma unroll
        for (int mt = 0; mt < 4; mt++) {
            int r_in0 = wm * 64 + mt * 16 + (lane >> 2);
            #pragma unroll
            for (int half = 0; half < 2; half++) {
                int r_in = r_in0 + half * 8;
                int m = m0 + r_in;
                int g = r_in >> 5;
                const float4* pr = reinterpret_cast<const float4*>(Ps + r_in * 8);
                float4 p0 = pr[0], p1 = pr[1];
                #pragma unroll
                for (int nt = 0; nt < 4; nt++) {
                    int c_in = wn * 32 + nt * 8 + (lane & 3) * 2;
                    int n = n0 + c_in;
                    const float4* xb0 = reinterpret_cast<const float4*>(xbs + (g * 128 + c_in) * 8);
                    const float4* xb1 = reinterpret_cast<const float4*>(xbs + (g * 128 + c_in + 1) * 8);
                    float4 u0 = xb0[0], u1 = xb0[1], v0 = xb1[0], v1 = xb1[1];
                    float e0 = p0.x * u0.x + p0.y * u0.y + p0.z * u0.z + p0.w * u0.w
                             + p1.x * u1.x + p1.y * u1.y + p1.z * u1.z + p1.w * u1.w;
                    float e1 = p0.x * v0.x + p0.y * v0.y + p0.z * v0.z + p0.w * v0.w
                             + p1.x * v1.x + p1.y * v1.y + p1.z * v1.z + p1.w * v1.w;
                    const float2 xr = *reinterpret_cast<const float2*>(xres + (size_t)m * N + n);
                    float2 o;
                    o.x = xr.x + acc[mt][nt][half * 2 + 0] + e0;
                    o.y = xr.y + acc[mt][nt][half * 2 + 1] + e1;
                    *reinterpret_cast<float2*>(outf + (size_t)m * N + n) = o;
                }
            }
        }
    } else {
        #pragma unroll
        for (int mt = 0; mt < 4; mt++) {
            int r_in0 = wm * 64 + mt * 16 + (lane >> 2);
            #pragma unroll
            for (int half = 0; half < 2; half++) {
                int m = m0 + r_in0 + half * 8;
                #pragma unroll
                for (int nt = 0; nt < 4; nt++) {
                    int n = n0 + wn * 32 + nt * 8 + (lane & 3) * 2;
                    float v0 = acc[mt][nt][half * 2 + 0] + bias[n];
                    float v1 = acc[mt][nt][half * 2 + 1] + bias[n + 1];
                    if (MODE == 0) {
                        *reinterpret_cast<__half2*>(outh + (size_t)m * N + n) =
                            __floats2half2_rn(gelu_exact(v0), gelu_exact(v1));
                    } else {
                        float2 o; o.x = v0; o.y = v1;
                        *reinterpret_cast<float2*>(outf + (size_t)m * N + n) = o;
                    }
                }
            }
        }
    }
}

// ---------------------------------------------------------------------------
#define SMEM_STAGE2 (2 * (ATILE + BTILE))   // 37888

extern "C" void kernel_launch(void* const* d_in, const int* in_sizes, int n_in,
                              void* d_out, int out_size)
{
    const float* x    = (const float*)d_in[0];
    const float* ada  = (const float*)d_in[1];
    const float* base = (const float*)d_in[2];
    const float* w1   = (const float*)d_in[3];
    const float* b1   = (const float*)d_in[4];
    const float* w2   = (const float*)d_in[5];
    const float* b2   = (const float*)d_in[6];
    const float* ln_g = (const float*)d_in[7];
    const float* ln_b = (const float*)d_in[8];
    float* out = (float*)d_out;

    __half *ae, *h;
    float *xw, *Pp;
    cudaGetSymbolAddress((void**)&ae, g_ae);
    cudaGetSymbolAddress((void**)&h,  g_h);
    cudaGetSymbolAddress((void**)&xw, g_xw);
    cudaGetSymbolAddress((void**)&Pp, g_Ppart);

    cudaFuncSetAttribute(gemm_kernel<0>, cudaFuncAttributeMaxDynamicSharedMemorySize, SMEM_STAGE2);
    cudaFuncSetAttribute(gemm_kernel<1>, cudaFuncAttributeMaxDynamicSharedMemorySize, SMEM_STAGE2);
    cudaFuncSetAttribute(gemm_kernel<2>, cudaFuncAttributeMaxDynamicSharedMemorySize, SMEM_STAGE2);

    layernorm_kernel<<<NB, 256>>>(ada, ln_g, ln_b, ae);
    gemm_kernel<0><<<dim3(NINTER / BN, 1), 256, SMEM_STAGE2>>>(
        ae, w1, NINTER, b1, nullptr, h, nullptr, nullptr, nullptr);
    gemm_kernel<1><<<dim3(2 * ND * NRANK / BN, 1), 256, SMEM_STAGE2>>>(
        h, w2, 2 * ND * NRANK, b2, xw, nullptr, nullptr, nullptr, nullptr);
    p_partial_kernel<<<dim3(NB, PCHUNKS), 256>>>(x, xw, Pp);
    gemm_kernel<2><<<dim3(ND / BN, NB * NT / BM), 256, SMEM_STAGE2>>>(
        x, base, ND, nullptr, out, nullptr, x, Pp, xw);
}

// round 6
// speedup vs baseline: 4.5554x; 1.0435x over previous
#include <cuda_runtime.h>
#include <cuda_fp16.h>
#include <cstdint>
#include <math.h>

#define NB     128
#define NT     32
#define ND     1024
#define NADA   1024
#define NINTER 1024
#define NRANK  8
#define GK     1024
#define BM     128
#define BN     128
#define BK     32
#define SRA    80            // A row: 32 halves (64B) + 16B pad
#define SRB    272           // B row: 128 halves (256B) + 16B pad
#define ATILE  (128 * SRA)   // 10240
#define BTILE  (32 * SRB)    // 8704
#define STAGE  (ATILE + BTILE)
#define SMEM_SZ (2 * STAGE)  // 37888
#define PCHUNKS 16
#define PSZ    (NB * NT * NRANK)   // 32768
#define KSPLIT 4

// ---------------- scratch ----------------------------------------------------
__device__ __half g_ae[NB * NADA];
__device__ __half g_h[NB * NINTER];
__device__ __half g_x16[NB * NT * ND];
__device__ __half g_base16[ND * ND];
__device__ float  g_hpart[KSPLIT * NB * NINTER];
__device__ float  g_xw[NB * 2 * ND * NRANK];
__device__ float  g_Ppart[PCHUNKS * PSZ];

// ---------------- PTX helpers -------------------------------------------------
__device__ __forceinline__ uint32_t smem_u32(const void* p) {
    uint32_t a;
    asm("{ .reg .u64 t; cvta.to.shared.u64 t, %1; cvt.u32.u64 %0, t; }" : "=r"(a) : "l"(p));
    return a;
}
#define LDSM4(r, addr) \
    asm volatile("ldmatrix.sync.aligned.m8n8.x4.shared.b16 {%0,%1,%2,%3}, [%4];" \
        : "=r"((r)[0]), "=r"((r)[1]), "=r"((r)[2]), "=r"((r)[3]) : "r"(addr))
#define LDSM4T(r, addr) \
    asm volatile("ldmatrix.sync.aligned.m8n8.x4.trans.shared.b16 {%0,%1,%2,%3}, [%4];" \
        : "=r"((r)[0]), "=r"((r)[1]), "=r"((r)[2]), "=r"((r)[3]) : "r"(addr))
#define MMA_F16(d, a, b0, b1) \
    asm volatile("mma.sync.aligned.m16n8k16.row.col.f32.f16.f16.f32 " \
        "{%0,%1,%2,%3},{%4,%5,%6,%7},{%8,%9},{%0,%1,%2,%3};" \
        : "+f"((d)[0]), "+f"((d)[1]), "+f"((d)[2]), "+f"((d)[3]) \
        : "r"((a)[0]), "r"((a)[1]), "r"((a)[2]), "r"((a)[3]), "r"(b0), "r"(b1))

__device__ __forceinline__ float gelu_exact(float v) {
    return 0.5f * v * (1.0f + erff(v * 0.70710678118654752f));
}

// ---------------- fp32 -> fp16 conversion ------------------------------------
__global__ __launch_bounds__(256) void cvt16_kernel(
    const float4* __restrict__ src, __half* __restrict__ dst, int n4)
{
    int i = blockIdx.x * 256 + threadIdx.x;
    if (i >= n4) return;
    float4 v = src[i];
    __half2 hh[2] = { __floats2half2_rn(v.x, v.y), __floats2half2_rn(v.z, v.w) };
    *reinterpret_cast<uint2*>(dst + (size_t)i * 4) = *reinterpret_cast<uint2*>(hh);
}

// ---------------- layernorm (writes fp16) -------------------------------------
__global__ __launch_bounds__(256) void layernorm_kernel(
    const float* __restrict__ ada, const float* __restrict__ gamma,
    const float* __restrict__ beta, __half* __restrict__ outh)
{
    int row = blockIdx.x;
    const float4 v = reinterpret_cast<const float4*>(ada + (size_t)row * NADA)[threadIdx.x];
    float s  = v.x + v.y + v.z + v.w;
    float ss = v.x * v.x + v.y * v.y + v.z * v.z + v.w * v.w;
    __shared__ float rs[8], rq[8];
    #pragma unroll
    for (int o = 16; o > 0; o >>= 1) {
        s  += __shfl_xor_sync(0xFFFFFFFFu, s, o);
        ss += __shfl_xor_sync(0xFFFFFFFFu, ss, o);
    }
    int warp = threadIdx.x >> 5, lane = threadIdx.x & 31;
    if (lane == 0) { rs[warp] = s; rq[warp] = ss; }
    __syncthreads();
    float sum = 0.f, sumsq = 0.f;
    #pragma unroll
    for (int i = 0; i < 8; i++) { sum += rs[i]; sumsq += rq[i]; }
    const float inv_n = 1.0f / NADA;
    float mu = sum * inv_n;
    float rstd = rsqrtf(sumsq * inv_n - mu * mu + 1e-5f);
    const float4 gv = reinterpret_cast<const float4*>(gamma)[threadIdx.x];
    const float4 bv = reinterpret_cast<const float4*>(beta)[threadIdx.x];
    float o0 = (v.x - mu) * rstd * gv.x + bv.x;
    float o1 = (v.y - mu) * rstd * gv.y + bv.y;
    float o2 = (v.z - mu) * rstd * gv.z + bv.z;
    float o3 = (v.w - mu) * rstd * gv.w + bv.w;
    __half2 hh[2] = { __floats2half2_rn(o0, o1), __floats2half2_rn(o2, o3) };
    *reinterpret_cast<uint2*>(outh + (size_t)row * NADA + threadIdx.x * 4) =
        *reinterpret_cast<uint2*>(hh);
}

// ---------------- reduce split-K partials + bias + GELU -> fp16 ---------------
__global__ __launch_bounds__(256) void reduce_gelu_kernel(
    const float* __restrict__ part, const float* __restrict__ b1,
    __half* __restrict__ h)
{
    int i = blockIdx.x * 256 + threadIdx.x;          // float4 index, 32768 total
    const float4* p = reinterpret_cast<const float4*>(part);
    float4 s = p[i];
    #pragma unroll
    for (int z = 1; z < KSPLIT; z++) {
        float4 t = p[(size_t)z * (NB * NINTER / 4) + i];
        s.x += t.x; s.y += t.y; s.z += t.z; s.w += t.w;
    }
    const float4 bb = reinterpret_cast<const float4*>(b1)[i & (NINTER / 4 - 1)];
    float g0 = gelu_exact(s.x + bb.x), g1 = gelu_exact(s.y + bb.y);
    float g2 = gelu_exact(s.z + bb.z), g3 = gelu_exact(s.w + bb.w);
    __half2 hh[2] = { __floats2half2_rn(g0, g1), __floats2half2_rn(g2, g3) };
    *reinterpret_cast<uint2*>(h + (size_t)i * 4) = *reinterpret_cast<uint2*>(hh);
}

// ---------------- partial P: grid (b, chunk of 64 d), xa from global ----------
__global__ __launch_bounds__(256) void p_partial_kernel(
    const float* __restrict__ x, const float* __restrict__ xw, float* __restrict__ Pp)
{
    int b = blockIdx.x, cch = blockIdx.y;
    int w = threadIdx.x >> 5, lane = threadIdx.x & 31;
    const float* xa = xw + (size_t)b * (2 * ND * NRANK) + cch * 64 * NRANK;
    #pragma unroll
    for (int t = w; t < NT; t += 8) {
        const float* xrow = x + ((size_t)b * NT + t) * ND + cch * 64;
        float acc[8] = {0, 0, 0, 0, 0, 0, 0, 0};
        #pragma unroll
        for (int ds = 0; ds < 2; ds++) {
            int d = ds * 32 + lane;
            float xv = xrow[d];
            float4 a0 = *reinterpret_cast<const float4*>(xa + d * 8);
            float4 a1 = *reinterpret_cast<const float4*>(xa + d * 8 + 4);
            acc[0] += xv * a0.x; acc[1] += xv * a0.y;
            acc[2] += xv * a0.z; acc[3] += xv * a0.w;
            acc[4] += xv * a1.x; acc[5] += xv * a1.y;
            acc[6] += xv * a1.z; acc[7] += xv * a1.w;
        }
        #pragma unroll
        for (int r = 0; r < 8; r++) {
            float sv = acc[r];
            #pragma unroll
            for (int o = 16; o > 0; o >>= 1) sv += __shfl_xor_sync(0xFFFFFFFFu, sv, o);
            if (lane == r) Pp[(size_t)cch * PSZ + ((size_t)b * NT + t) * NRANK + r] = sv;
        }
    }
}

// ---------------- fp16 HMMA GEMM ----------------------------------------------
// MODE 0: A fp16, B fp32->fp16; split-K raw fp32 partials (z = blockIdx.z)
// MODE 1: A fp16, B fp32->fp16; epi: +bias -> fp32
// MODE 2: A fp16, B fp16;       epi: +xres + P@x_b^T -> fp32
template<int MODE, int NIT>
__global__ __launch_bounds__(256) void gemm_kernel(
    const __half* __restrict__ A, const void* __restrict__ Bp, int N,
    const float* __restrict__ bias, float* __restrict__ outf,
    const float* __restrict__ xres, const float* __restrict__ Pp,
    const float* __restrict__ xw)
{
    extern __shared__ char smem[];
    const int tid = threadIdx.x, wid = tid >> 5, lane = tid & 31;
    const int m0 = blockIdx.y * BM, n0 = blockIdx.x * BN;
    const int kb = (MODE == 0) ? blockIdx.z * (NIT * BK) : 0;
    const int wm = wid & 1, wn = wid >> 1;
    const uint32_t sb = smem_u32(smem);

    float acc[4][4][4];
    #pragma unroll
    for (int i = 0; i < 4; i++)
        #pragma unroll
        for (int j = 0; j < 4; j++)
            #pragma unroll
            for (int e = 0; e < 4; e++) acc[i][j][e] = 0.f;

    uint4  ra[2];
    float4 rb32[4];
    uint4  rb16[2];

    auto loadA = [&](int k0) {
        #pragma unroll
        for (int i = 0; i < 2; i++) {
            int ch = tid + i * 256, r = ch >> 2, c = ch & 3;
            ra[i] = *reinterpret_cast<const uint4*>(A + (size_t)(m0 + r) * GK + kb + k0 + c * 8);
        }
    };
    auto loadB = [&](int k0) {
        if (MODE == 2) {
            const __half* B = (const __half*)Bp;
            #pragma unroll
            for (int i = 0; i < 2; i++) {
                int ch = tid + i * 256, r = ch >> 4, c = ch & 15;
                rb16[i] = *reinterpret_cast<const uint4*>(B + (size_t)(kb + k0 + r) * N + n0 + c * 8);
            }
        } else {
            const float* B = (const float*)Bp;
            #pragma unroll
            for (int i = 0; i < 4; i++) {
                int ch = tid + i * 256, r = ch >> 5, c = ch & 31;
                rb32[i] = *reinterpret_cast<const float4*>(B + (size_t)(kb + k0 + r) * N + n0 + c * 4);
            }
        }
    };
    auto storeA = [&](int s) {
        char* stg = smem + s * STAGE;
        #pragma unroll
        for (int i = 0; i < 2; i++) {
            int ch = tid + i * 256, r = ch >> 2, c = ch & 3;
            *reinterpret_cast<uint4*>(stg + r * SRA + c * 16) = ra[i];
        }
    };
    auto storeB = [&](int s) {
        char* stg = smem + s * STAGE + ATILE;
        if (MODE == 2) {
            #pragma unroll
            for (int i = 0; i < 2; i++) {
                int ch = tid + i * 256, r = ch >> 4, c = ch & 15;
                *reinterpret_cast<uint4*>(stg + r * SRB + c * 16) = rb16[i];
            }
        } else {
            #pragma unroll
            for (int i = 0; i < 4; i++) {
                int ch = tid + i * 256, r = ch >> 5, c = ch & 31;
                float4 v = rb32[i];
                __half2 hh[2] = { __floats2half2_rn(v.x, v.y), __floats2half2_rn(v.z, v.w) };
                *reinterpret_cast<uint2*>(stg + r * SRB + c * 8) = *reinterpret_cast<uint2*>(hh);
            }
        }
    };

    const int a_row  = wm * 64 + (lane & 15);
    const int a_off  = (lane >> 4) * 16;
    const int b_row  = lane & 15;
    const int b_colb = wn * 64 + (lane >> 4) * 16;

    auto compute = [&](int s) {
        uint32_t base = sb + s * STAGE;
        #pragma unroll
        for (int ks = 0; ks < 2; ks++) {
            uint32_t af[4][4];
            #pragma unroll
            for (int mt = 0; mt < 4; mt++)
                LDSM4(af[mt], base + (a_row + mt * 16) * SRA + ks * 32 + a_off);
            uint32_t bf[4][2];
            #pragma unroll
            for (int pr = 0; pr < 2; pr++) {
                uint32_t r[4];
                LDSM4T(r, base + ATILE + (ks * 16 + b_row) * SRB + b_colb + pr * 32);
                bf[pr * 2 + 0][0] = r[0]; bf[pr * 2 + 0][1] = r[1];
                bf[pr * 2 + 1][0] = r[2]; bf[pr * 2 + 1][1] = r[3];
            }
            #pragma unroll
            for (int mt = 0; mt < 4; mt++)
                #pragma unroll
                for (int nt = 0; nt < 4; nt++)
                    MMA_F16(acc[mt][nt], af[mt], bf[nt][0], bf[nt][1]);
        }
    };

    // prologue
    loadA(0); loadB(0);
    storeA(0); storeB(0);
    loadA(BK); loadB(BK);
    __syncthreads();

    for (int c = 0; c < NIT; c++) {
        compute(c & 1);
        if (c + 1 < NIT) { storeA((c + 1) & 1); storeB((c + 1) & 1); }
        if (c + 2 < NIT) { loadA((c + 2) * BK); loadB((c + 2) * BK); }
        __syncthreads();
    }

    // ---------------- epilogue ----------------
    if (MODE == 2) {
        float* Ps  = reinterpret_cast<float*>(smem);          // 4 KB
        float* xbs = reinterpret_cast<float*>(smem + 4096);   // 16 KB
        for (int i = tid; i < BM * NRANK; i += 256) {
            float sv = 0.f;
            #pragma unroll
            for (int c = 0; c < PCHUNKS; c++)
                sv += Pp[(size_t)c * PSZ + (size_t)m0 * NRANK + i];
            Ps[i] = sv;
        }
        for (int i = tid; i < 4 * BN * NRANK; i += 256) {
            int g = i >> 10, j = (i >> 3) & 127, r = i & 7;
            int bg = (m0 >> 5) + g;
            xbs[i] = xw[(size_t)bg * (2 * ND * NRANK) + ND * NRANK + (size_t)(n0 + j) * NRANK + r];
        }
        __syncthreads();

        #pragma unroll
        for (int mt = 0; mt < 4; mt++) {
            int r_in0 = wm * 64 + mt * 16 + (lane >> 2);
            #pragma unroll
            for (int half = 0; half < 2; half++) {
                int r_in = r_in0 + half * 8;
                int m = m0 + r_in;
                int g = r_in >> 5;
                const float4* pr = reinterpret_cast<const float4*>(Ps + r_in * 8);
                float4 p0 = pr[0], p1 = pr[1];
                #pragma unroll
                for (int nt = 0; nt < 4; nt++) {
                    int c_in = wn * 32 + nt * 8 + (lane & 3) * 2;
                    int n = n0 + c_in;
                    const float4* xb0 = reinterpret_cast<const float4*>(xbs + (g * 128 + c_in) * 8);
                    const float4* xb1 = reinterpret_cast<const float4*>(xbs + (g * 128 + c_in + 1) * 8);
                    float4 u0 = xb0[0], u1 = xb0[1], v0 = xb1[0], v1 = xb1[1];
                    float e0 = p0.x * u0.x + p0.y * u0.y + p0.z * u0.z + p0.w * u0.w
                             + p1.x * u1.x + p1.y * u1.y + p1.z * u1.z + p1.w * u1.w;
                    float e1 = p0.x * v0.x + p0.y * v0.y + p0.z * v0.z + p0.w * v0.w
                             + p1.x * v1.x + p1.y * v1.y + p1.z * v1.z + p1.w * v1.w;
                    const float2 xr = *reinterpret_cast<const float2*>(xres + (size_t)m * N + n);
                    float2 o;
                    o.x = xr.x + acc[mt][nt][half * 2 + 0] + e0;
                    o.y = xr.y + acc[mt][nt][half * 2 + 1] + e1;
                    *reinterpret_cast<float2*>(outf + (size_t)m * N + n) = o;
                }
            }
        }
    } else {
        float* po = outf;
        if (MODE == 0) po += (size_t)blockIdx.z * (NB * NINTER);
        #pragma unroll
        for (int mt = 0; mt < 4; mt++) {
            int r_in0 = wm * 64 + mt * 16 + (lane >> 2);
            #pragma unroll
            for (int half = 0; half < 2; half++) {
                int m = m0 + r_in0 + half * 8;
                #pragma unroll
                for (int nt = 0; nt < 4; nt++) {
                    int n = n0 + wn * 32 + nt * 8 + (lane & 3) * 2;
                    float v0 = acc[mt][nt][half * 2 + 0];
                    float v1 = acc[mt][nt][half * 2 + 1];
                    if (MODE == 1) { v0 += bias[n]; v1 += bias[n + 1]; }
                    float2 o; o.x = v0; o.y = v1;
                    *reinterpret_cast<float2*>(po + (size_t)m * N + n) = o;
                }
            }
        }
    }
}

// ---------------------------------------------------------------------------
extern "C" void kernel_launch(void* const* d_in, const int* in_sizes, int n_in,
                              void* d_out, int out_size)
{
    const float* x    = (const float*)d_in[0];
    const float* ada  = (const float*)d_in[1];
    const float* base = (const float*)d_in[2];
    const float* w1   = (const float*)d_in[3];
    const float* b1   = (const float*)d_in[4];
    const float* w2   = (const float*)d_in[5];
    const float* b2   = (const float*)d_in[6];
    const float* ln_g = (const float*)d_in[7];
    const float* ln_b = (const float*)d_in[8];
    float* out = (float*)d_out;

    __half *ae, *h, *x16, *base16;
    float *xw, *Pp, *hpart;
    cudaGetSymbolAddress((void**)&ae, g_ae);
    cudaGetSymbolAddress((void**)&h,  g_h);
    cudaGetSymbolAddress((void**)&x16, g_x16);
    cudaGetSymbolAddress((void**)&base16, g_base16);
    cudaGetSymbolAddress((void**)&hpart, g_hpart);
    cudaGetSymbolAddress((void**)&xw, g_xw);
    cudaGetSymbolAddress((void**)&Pp, g_Ppart);

    cudaFuncSetAttribute(gemm_kernel<0, 8>,  cudaFuncAttributeMaxDynamicSharedMemorySize, SMEM_SZ);
    cudaFuncSetAttribute(gemm_kernel<1, 32>, cudaFuncAttributeMaxDynamicSharedMemorySize, SMEM_SZ);
    cudaFuncSetAttribute(gemm_kernel<2, 32>, cudaFuncAttributeMaxDynamicSharedMemorySize, SMEM_SZ);

    // one-time fp16 conversions (independent of hypernetwork path)
    cvt16_kernel<<<(NB * NT * ND / 4 + 255) / 256, 256>>>((const float4*)x, x16, NB * NT * ND / 4);
    cvt16_kernel<<<(ND * ND / 4 + 255) / 256, 256>>>((const float4*)base, base16, ND * ND / 4);

    // hypernetwork
    layernorm_kernel<<<NB, 256>>>(ada, ln_g, ln_b, ae);
    gemm_kernel<0, 8><<<dim3(NINTER / BN, 1, KSPLIT), 256, SMEM_SZ>>>(
        ae, w1, NINTER, nullptr, hpart, nullptr, nullptr, nullptr);
    reduce_gelu_kernel<<<NB * NINTER / 4 / 256, 256>>>(hpart, b1, h);
    gemm_kernel<1, 32><<<dim3(2 * ND * NRANK / BN, 1), 256, SMEM_SZ>>>(
        h, w2, 2 * ND * NRANK, b2, xw, nullptr, nullptr, nullptr);

    // low-rank path + fused final GEMM
    p_partial_kernel<<<dim3(NB, PCHUNKS), 256>>>(x, xw, Pp);
    gemm_kernel<2, 32><<<dim3(ND / BN, NB * NT / BM), 256, SMEM_SZ>>>(
        x16, base16, ND, nullptr, out, x, Pp, xw);
}

// round 7
// speedup vs baseline: 5.4121x; 1.1881x over previous
#include <cuda_runtime.h>
#include <cuda_fp16.h>
#include <cstdint>
#include <math.h>

#define NB     128
#define NT     32
#define ND     1024
#define NADA   1024
#define NINTER 1024
#define NRANK  8
#define GK     1024
#define BM     128
#define BN     128
#define BK     32
#define SRA    80            // A row: 32 halves (64B) + 16B pad
#define SRB    272           // B row: 128 halves (256B) + 16B pad
#define ATILE  (128 * SRA)   // 10240
#define BTILE  (32 * SRB)    // 8704
#define STAGE  (ATILE + BTILE)
#define SMEM_SZ (2 * STAGE)  // 37888
#define PCHUNKS 16
#define PSZ    (NB * NT * NRANK)   // 32768
#define KSPLIT 8

// ---- final GEMM (cp.async, BK=64, 3 stages) ----
#define FBK    64
#define FNIT   (GK / FBK)    // 16
#define FSRA   144           // 128B data + 16B pad
#define FSRB   272           // 256B data + 16B pad
#define FATILE (128 * FSRA)  // 18432
#define FBTILE (64 * FSRB)   // 17408
#define FSTAGE (FATILE + FBTILE)   // 35840
#define FSMEM  (3 * FSTAGE)        // 107520

// ---------------- scratch ----------------------------------------------------
__device__ __half g_ae[NB * NADA];
__device__ __half g_h[NB * NINTER];
__device__ __half g_x16[NB * NT * ND];
__device__ __half g_base16[ND * ND];
__device__ float  g_hpart[KSPLIT * NB * NINTER];
__device__ float  g_xw[NB * 2 * ND * NRANK];
__device__ float  g_Ppart[PCHUNKS * PSZ];

// ---------------- PTX helpers -------------------------------------------------
__device__ __forceinline__ uint32_t smem_u32(const void* p) {
    uint32_t a;
    asm("{ .reg .u64 t; cvta.to.shared.u64 t, %1; cvt.u32.u64 %0, t; }" : "=r"(a) : "l"(p));
    return a;
}
#define CP16(sa, ga) \
    asm volatile("cp.async.cg.shared.global [%0], [%1], 16;" :: "r"(sa), "l"(ga))
#define CP_COMMIT() asm volatile("cp.async.commit_group;")
#define CP_WAIT(n)  asm volatile("cp.async.wait_group %0;" :: "n"(n))
#define LDSM4(r, addr) \
    asm volatile("ldmatrix.sync.aligned.m8n8.x4.shared.b16 {%0,%1,%2,%3}, [%4];" \
        : "=r"((r)[0]), "=r"((r)[1]), "=r"((r)[2]), "=r"((r)[3]) : "r"(addr))
#define LDSM4T(r, addr) \
    asm volatile("ldmatrix.sync.aligned.m8n8.x4.trans.shared.b16 {%0,%1,%2,%3}, [%4];" \
        : "=r"((r)[0]), "=r"((r)[1]), "=r"((r)[2]), "=r"((r)[3]) : "r"(addr))
#define MMA_F16(d, a, b0, b1) \
    asm volatile("mma.sync.aligned.m16n8k16.row.col.f32.f16.f16.f32 " \
        "{%0,%1,%2,%3},{%4,%5,%6,%7},{%8,%9},{%0,%1,%2,%3};" \
        : "+f"((d)[0]), "+f"((d)[1]), "+f"((d)[2]), "+f"((d)[3]) \
        : "r"((a)[0]), "r"((a)[1]), "r"((a)[2]), "r"((a)[3]), "r"(b0), "r"(b1))

__device__ __forceinline__ float gelu_exact(float v) {
    return 0.5f * v * (1.0f + erff(v * 0.70710678118654752f));
}

// ---------------- fp32 -> fp16 conversion ------------------------------------
__global__ __launch_bounds__(256) void cvt16_kernel(
    const float4* __restrict__ src, __half* __restrict__ dst, int n4)
{
    int i = blockIdx.x * 256 + threadIdx.x;
    if (i >= n4) return;
    float4 v = src[i];
    __half2 hh[2] = { __floats2half2_rn(v.x, v.y), __floats2half2_rn(v.z, v.w) };
    *reinterpret_cast<uint2*>(dst + (size_t)i * 4) = *reinterpret_cast<uint2*>(hh);
}

// ---------------- layernorm (writes fp16) -------------------------------------
__global__ __launch_bounds__(256) void layernorm_kernel(
    const float* __restrict__ ada, const float* __restrict__ gamma,
    const float* __restrict__ beta, __half* __restrict__ outh)
{
    int row = blockIdx.x;
    const float4 v = reinterpret_cast<const float4*>(ada + (size_t)row * NADA)[threadIdx.x];
    float s  = v.x + v.y + v.z + v.w;
    float ss = v.x * v.x + v.y * v.y + v.z * v.z + v.w * v.w;
    __shared__ float rs[8], rq[8];
    #pragma unroll
    for (int o = 16; o > 0; o >>= 1) {
        s  += __shfl_xor_sync(0xFFFFFFFFu, s, o);
        ss += __shfl_xor_sync(0xFFFFFFFFu, ss, o);
    }
    int warp = threadIdx.x >> 5, lane = threadIdx.x & 31;
    if (lane == 0) { rs[warp] = s; rq[warp] = ss; }
    __syncthreads();
    float sum = 0.f, sumsq = 0.f;
    #pragma unroll
    for (int i = 0; i < 8; i++) { sum += rs[i]; sumsq += rq[i]; }
    const float inv_n = 1.0f / NADA;
    float mu = sum * inv_n;
    float rstd = rsqrtf(sumsq * inv_n - mu * mu + 1e-5f);
    const float4 gv = reinterpret_cast<const float4*>(gamma)[threadIdx.x];
    const float4 bv = reinterpret_cast<const float4*>(beta)[threadIdx.x];
    float o0 = (v.x - mu) * rstd * gv.x + bv.x;
    float o1 = (v.y - mu) * rstd * gv.y + bv.y;
    float o2 = (v.z - mu) * rstd * gv.z + bv.z;
    float o3 = (v.w - mu) * rstd * gv.w + bv.w;
    __half2 hh[2] = { __floats2half2_rn(o0, o1), __floats2half2_rn(o2, o3) };
    *reinterpret_cast<uint2*>(outh + (size_t)row * NADA + threadIdx.x * 4) =
        *reinterpret_cast<uint2*>(hh);
}

// ---------------- reduce split-K partials + bias + GELU -> fp16 ---------------
__global__ __launch_bounds__(256) void reduce_gelu_kernel(
    const float* __restrict__ part, const float* __restrict__ b1,
    __half* __restrict__ h)
{
    int i = blockIdx.x * 256 + threadIdx.x;          // float4 index, 32768 total
    const float4* p = reinterpret_cast<const float4*>(part);
    float4 s = p[i];
    #pragma unroll
    for (int z = 1; z < KSPLIT; z++) {
        float4 t = p[(size_t)z * (NB * NINTER / 4) + i];
        s.x += t.x; s.y += t.y; s.z += t.z; s.w += t.w;
    }
    const float4 bb = reinterpret_cast<const float4*>(b1)[i & (NINTER / 4 - 1)];
    float g0 = gelu_exact(s.x + bb.x), g1 = gelu_exact(s.y + bb.y);
    float g2 = gelu_exact(s.z + bb.z), g3 = gelu_exact(s.w + bb.w);
    __half2 hh[2] = { __floats2half2_rn(g0, g1), __floats2half2_rn(g2, g3) };
    *reinterpret_cast<uint2*>(h + (size_t)i * 4) = *reinterpret_cast<uint2*>(hh);
}

// ---------------- partial P: grid (b, chunk of 64 d), x in fp16 ----------------
__global__ __launch_bounds__(256) void p_partial_kernel(
    const __half* __restrict__ x16, const float* __restrict__ xw, float* __restrict__ Pp)
{
    int b = blockIdx.x, cch = blockIdx.y;
    int w = threadIdx.x >> 5, lane = threadIdx.x & 31;
    const float* xa = xw + (size_t)b * (2 * ND * NRANK) + cch * 64 * NRANK;
    #pragma unroll
    for (int t = w; t < NT; t += 8) {
        const __half* xrow = x16 + ((size_t)b * NT + t) * ND + cch * 64;
        float acc[8] = {0, 0, 0, 0, 0, 0, 0, 0};
        #pragma unroll
        for (int ds = 0; ds < 2; ds++) {
            int d = ds * 32 + lane;
            float xv = __half2float(xrow[d]);
            float4 a0 = *reinterpret_cast<const float4*>(xa + d * 8);
            float4 a1 = *reinterpret_cast<const float4*>(xa + d * 8 + 4);
            acc[0] += xv * a0.x; acc[1] += xv * a0.y;
            acc[2] += xv * a0.z; acc[3] += xv * a0.w;
            acc[4] += xv * a1.x; acc[5] += xv * a1.y;
            acc[6] += xv * a1.z; acc[7] += xv * a1.w;
        }
        #pragma unroll
        for (int r = 0; r < 8; r++) {
            float sv = acc[r];
            #pragma unroll
            for (int o = 16; o > 0; o >>= 1) sv += __shfl_xor_sync(0xFFFFFFFFu, sv, o);
            if (lane == r) Pp[(size_t)cch * PSZ + ((size_t)b * NT + t) * NRANK + r] = sv;
        }
    }
}

// ---------------- hypernetwork HMMA GEMM (register-prefetch path) -------------
// MODE 0: split-K raw fp32 partials (z = blockIdx.z)
// MODE 1: +bias -> fp32
template<int MODE, int NIT>
__global__ __launch_bounds__(256) void gemm_kernel(
    const __half* __restrict__ A, const float* __restrict__ B, int N,
    const float* __restrict__ bias, float* __restrict__ outf)
{
    extern __shared__ char smem[];
    const int tid = threadIdx.x, wid = tid >> 5, lane = tid & 31;
    const int m0 = blockIdx.y * BM, n0 = blockIdx.x * BN;
    const int kb = (MODE == 0) ? blockIdx.z * (NIT * BK) : 0;
    const int wm = wid & 1, wn = wid >> 1;
    const uint32_t sb = smem_u32(smem);

    float acc[4][4][4];
    #pragma unroll
    for (int i = 0; i < 4; i++)
        #pragma unroll
        for (int j = 0; j < 4; j++)
            #pragma unroll
            for (int e = 0; e < 4; e++) acc[i][j][e] = 0.f;

    uint4  ra[2];
    float4 rb32[4];

    auto loadA = [&](int k0) {
        #pragma unroll
        for (int i = 0; i < 2; i++) {
            int ch = tid + i * 256, r = ch >> 2, c = ch & 3;
            ra[i] = *reinterpret_cast<const uint4*>(A + (size_t)(m0 + r) * GK + kb + k0 + c * 8);
        }
    };
    auto loadB = [&](int k0) {
        #pragma unroll
        for (int i = 0; i < 4; i++) {
            int ch = tid + i * 256, r = ch >> 5, c = ch & 31;
            rb32[i] = *reinterpret_cast<const float4*>(B + (size_t)(kb + k0 + r) * N + n0 + c * 4);
        }
    };
    auto storeA = [&](int s) {
        char* stg = smem + s * STAGE;
        #pragma unroll
        for (int i = 0; i < 2; i++) {
            int ch = tid + i * 256, r = ch >> 2, c = ch & 3;
            *reinterpret_cast<uint4*>(stg + r * SRA + c * 16) = ra[i];
        }
    };
    auto storeB = [&](int s) {
        char* stg = smem + s * STAGE + ATILE;
        #pragma unroll
        for (int i = 0; i < 4; i++) {
            int ch = tid + i * 256, r = ch >> 5, c = ch & 31;
            float4 v = rb32[i];
            __half2 hh[2] = { __floats2half2_rn(v.x, v.y), __floats2half2_rn(v.z, v.w) };
            *reinterpret_cast<uint2*>(stg + r * SRB + c * 8) = *reinterpret_cast<uint2*>(hh);
        }
    };

    const int a_row  = wm * 64 + (lane & 15);
    const int a_off  = (lane >> 4) * 16;
    const int b_row  = lane & 15;
    const int b_colb = wn * 64 + (lane >> 4) * 16;

    auto compute = [&](int s) {
        uint32_t base = sb + s * STAGE;
        #pragma unroll
        for (int ks = 0; ks < 2; ks++) {
            uint32_t af[4][4];
            #pragma unroll
            for (int mt = 0; mt < 4; mt++)
                LDSM4(af[mt], base + (a_row + mt * 16) * SRA + ks * 32 + a_off);
            uint32_t bf[4][2];
            #pragma unroll
            for (int pr = 0; pr < 2; pr++) {
                uint32_t r[4];
                LDSM4T(r, base + ATILE + (ks * 16 + b_row) * SRB + b_colb + pr * 32);
                bf[pr * 2 + 0][0] = r[0]; bf[pr * 2 + 0][1] = r[1];
                bf[pr * 2 + 1][0] = r[2]; bf[pr * 2 + 1][1] = r[3];
            }
            #pragma unroll
            for (int mt = 0; mt < 4; mt++)
                #pragma unroll
                for (int nt = 0; nt < 4; nt++)
                    MMA_F16(acc[mt][nt], af[mt], bf[nt][0], bf[nt][1]);
        }
    };

    loadA(0); loadB(0);
    storeA(0); storeB(0);
    if (NIT > 1) { loadA(BK); loadB(BK); }
    __syncthreads();

    for (int c = 0; c < NIT; c++) {
        compute(c & 1);
        if (c + 1 < NIT) { storeA((c + 1) & 1); storeB((c + 1) & 1); }
        if (c + 2 < NIT) { loadA((c + 2) * BK); loadB((c + 2) * BK); }
        __syncthreads();
    }

    float* po = outf;
    if (MODE == 0) po += (size_t)blockIdx.z * (NB * NINTER);
    #pragma unroll
    for (int mt = 0; mt < 4; mt++) {
        int r_in0 = wm * 64 + mt * 16 + (lane >> 2);
        #pragma unroll
        for (int half = 0; half < 2; half++) {
            int m = m0 + r_in0 + half * 8;
            #pragma unroll
            for (int nt = 0; nt < 4; nt++) {
                int n = n0 + wn * 32 + nt * 8 + (lane & 3) * 2;
                float v0 = acc[mt][nt][half * 2 + 0];
                float v1 = acc[mt][nt][half * 2 + 1];
                if (MODE == 1) { v0 += bias[n]; v1 += bias[n + 1]; }
                float2 o; o.x = v0; o.y = v1;
                *reinterpret_cast<float2*>(po + (size_t)m * N + n) = o;
            }
        }
    }
}

// ---------------- final GEMM: cp.async 3-stage, BK=64, occ 2 -------------------
// out = xres + A16 @ B16 + P @ x_b^T
__global__ __launch_bounds__(256, 2) void gemm_final_kernel(
    const __half* __restrict__ A, const __half* __restrict__ B,
    float* __restrict__ outf, const float* __restrict__ xres,
    const float* __restrict__ Pp, const float* __restrict__ xw)
{
    extern __shared__ char smem[];
    const int tid = threadIdx.x, wid = tid >> 5, lane = tid & 31;
    const int m0 = blockIdx.y * BM, n0 = blockIdx.x * BN;
    const int wm = wid & 1, wn = wid >> 1;
    const uint32_t sb = smem_u32(smem);
    const int N = ND;

    float acc[4][4][4];
    #pragma unroll
    for (int i = 0; i < 4; i++)
        #pragma unroll
        for (int j = 0; j < 4; j++)
            #pragma unroll
            for (int e = 0; e < 4; e++) acc[i][j][e] = 0.f;

    auto issue = [&](int c) {
        uint32_t st = sb + (c % 3) * FSTAGE;
        int k0 = c * FBK;
        #pragma unroll
        for (int i = 0; i < 4; i++) {          // A: 128 rows x 128B
            int ch = tid + i * 256, r = ch >> 3, cc = ch & 7;
            CP16(st + r * FSRA + cc * 16,
                 A + (size_t)(m0 + r) * GK + k0 + cc * 8);
        }
        #pragma unroll
        for (int i = 0; i < 4; i++) {          // B: 64 rows x 256B
            int ch = tid + i * 256, r = ch >> 4, cc = ch & 15;
            CP16(st + FATILE + r * FSRB + cc * 16,
                 B + (size_t)(k0 + r) * N + n0 + cc * 8);
        }
        CP_COMMIT();
    };

    const int a_row  = wm * 64 + (lane & 15);
    const int a_off  = (lane >> 4) * 16;
    const int b_row  = lane & 15;
    const int b_colb = wn * 64 + (lane >> 4) * 16;

    issue(0);
    issue(1);

    for (int c = 0; c < FNIT; c++) {
        if (c < FNIT - 1) CP_WAIT(1); else CP_WAIT(0);
        __syncthreads();
        if (c + 2 < FNIT) issue(c + 2);

        uint32_t base = sb + (c % 3) * FSTAGE;
        #pragma unroll
        for (int ks = 0; ks < 4; ks++) {
            uint32_t af[4][4];
            #pragma unroll
            for (int mt = 0; mt < 4; mt++)
                LDSM4(af[mt], base + (a_row + mt * 16) * FSRA + ks * 32 + a_off);
            uint32_t bf[4][2];
            #pragma unroll
            for (int pr = 0; pr < 2; pr++) {
                uint32_t r[4];
                LDSM4T(r, base + FATILE + (ks * 16 + b_row) * FSRB + b_colb + pr * 32);
                bf[pr * 2 + 0][0] = r[0]; bf[pr * 2 + 0][1] = r[1];
                bf[pr * 2 + 1][0] = r[2]; bf[pr * 2 + 1][1] = r[3];
            }
            #pragma unroll
            for (int mt = 0; mt < 4; mt++)
                #pragma unroll
                for (int nt = 0; nt < 4; nt++)
                    MMA_F16(acc[mt][nt], af[mt], bf[nt][0], bf[nt][1]);
        }
    }
    __syncthreads();

    // ---------------- epilogue: + xres + P @ x_b^T ----------------
    float* Ps  = reinterpret_cast<float*>(smem);          // 4 KB
    float* xbs = reinterpret_cast<float*>(smem + 4096);   // 16 KB
    for (int i = tid; i < BM * NRANK; i += 256) {
        float sv = 0.f;
        #pragma unroll
        for (int c = 0; c < PCHUNKS; c++)
            sv += Pp[(size_t)c * PSZ + (size_t)m0 * NRANK + i];
        Ps[i] = sv;
    }
    for (int i = tid; i < 4 * BN * NRANK; i += 256) {
        int g = i >> 10, j = (i >> 3) & 127, r = i & 7;
        int bg = (m0 >> 5) + g;
        xbs[i] = xw[(size_t)bg * (2 * ND * NRANK) + ND * NRANK + (size_t)(n0 + j) * NRANK + r];
    }
    __syncthreads();

    #pragma unroll
    for (int mt = 0; mt < 4; mt++) {
        int r_in0 = wm * 64 + mt * 16 + (lane >> 2);
        #pragma unroll
        for (int half = 0; half < 2; half++) {
            int r_in = r_in0 + half * 8;
            int m = m0 + r_in;
            int g = r_in >> 5;
            const float4* pr = reinterpret_cast<const float4*>(Ps + r_in * 8);
            float4 p0 = pr[0], p1 = pr[1];
            #pragma unroll
            for (int nt = 0; nt < 4; nt++) {
                int c_in = wn * 32 + nt * 8 + (lane & 3) * 2;
                int n = n0 + c_in;
                const float4* xb0 = reinterpret_cast<const float4*>(xbs + (g * 128 + c_in) * 8);
                const float4* xb1 = reinterpret_cast<const float4*>(xbs + (g * 128 + c_in + 1) * 8);
                float4 u0 = xb0[0], u1 = xb0[1], v0 = xb1[0], v1 = xb1[1];
                float e0 = p0.x * u0.x + p0.y * u0.y + p0.z * u0.z + p0.w * u0.w
                         + p1.x * u1.x + p1.y * u1.y + p1.z * u1.z + p1.w * u1.w;
                float e1 = p0.x * v0.x + p0.y * v0.y + p0.z * v0.z + p0.w * v0.w
                         + p1.x * v1.x + p1.y * v1.y + p1.z * v1.z + p1.w * v1.w;
                const float2 xr = *reinterpret_cast<const float2*>(xres + (size_t)m * N + n);
                float2 o;
                o.x = xr.x + acc[mt][nt][half * 2 + 0] + e0;
                o.y = xr.y + acc[mt][nt][half * 2 + 1] + e1;
                *reinterpret_cast<float2*>(outf + (size_t)m * N + n) = o;
            }
        }
    }
}

// ---------------------------------------------------------------------------
extern "C" void kernel_launch(void* const* d_in, const int* in_sizes, int n_in,
                              void* d_out, int out_size)
{
    const float* x    = (const float*)d_in[0];
    const float* ada  = (const float*)d_in[1];
    const float* base = (const float*)d_in[2];
    const float* w1   = (const float*)d_in[3];
    const float* b1   = (const float*)d_in[4];
    const float* w2   = (const float*)d_in[5];
    const float* b2   = (const float*)d_in[6];
    const float* ln_g = (const float*)d_in[7];
    const float* ln_b = (const float*)d_in[8];
    float* out = (float*)d_out;

    __half *ae, *h, *x16, *base16;
    float *xw, *Pp, *hpart;
    cudaGetSymbolAddress((void**)&ae, g_ae);
    cudaGetSymbolAddress((void**)&h,  g_h);
    cudaGetSymbolAddress((void**)&x16, g_x16);
    cudaGetSymbolAddress((void**)&base16, g_base16);
    cudaGetSymbolAddress((void**)&hpart, g_hpart);
    cudaGetSymbolAddress((void**)&xw, g_xw);
    cudaGetSymbolAddress((void**)&Pp, g_Ppart);

    cudaFuncSetAttribute(gemm_kernel<0, 4>,  cudaFuncAttributeMaxDynamicSharedMemorySize, SMEM_SZ);
    cudaFuncSetAttribute(gemm_kernel<1, 32>, cudaFuncAttributeMaxDynamicSharedMemorySize, SMEM_SZ);
    cudaFuncSetAttribute(gemm_final_kernel,  cudaFuncAttributeMaxDynamicSharedMemorySize, FSMEM);

    // one-time fp16 conversions
    cvt16_kernel<<<(NB * NT * ND / 4 + 255) / 256, 256>>>((const float4*)x, x16, NB * NT * ND / 4);
    cvt16_kernel<<<(ND * ND / 4 + 255) / 256, 256>>>((const float4*)base, base16, ND * ND / 4);

    // hypernetwork
    layernorm_kernel<<<NB, 256>>>(ada, ln_g, ln_b, ae);
    gemm_kernel<0, 4><<<dim3(NINTER / BN, 1, KSPLIT), 256, SMEM_SZ>>>(
        ae, w1, NINTER, nullptr, hpart);
    reduce_gelu_kernel<<<NB * NINTER / 4 / 256, 256>>>(hpart, b1, h);
    gemm_kernel<1, 32><<<dim3(2 * ND * NRANK / BN, 1), 256, SMEM_SZ>>>(
        h, w2, 2 * ND * NRANK, b2, xw);

    // low-rank path + fused final GEMM
    p_partial_kernel<<<dim3(NB, PCHUNKS), 256>>>(x16, xw, Pp);
    gemm_final_kernel<<<dim3(ND / BN, NB * NT / BM), 256, FSMEM>>>(
        x16, base16, out, x, Pp, xw);
}

// round 9
// speedup vs baseline: 5.7661x; 1.0654x over previous
#include <cuda_runtime.h>
#include <cuda_fp16.h>
#include <cstdint>
#include <math.h>

#define NB     128
#define NT     32
#define ND     1024
#define NADA   1024
#define NINTER 1024
#define NRANK  8
#define GK     1024
#define BM     128
#define BN     128
#define BK     32
#define SRA    80            // A row: 32 halves (64B) + 16B pad
#define ATILE  (128 * SRA)   // 10240
#define SRB32  528           // B fp32 row: 512B + 16B pad (132 floats)
#define B32TILE (32 * SRB32) // 16896
#define STG32  (ATILE + B32TILE)  // 27136
#define NSTG   4
#define SMEM32 (NSTG * STG32)     // 108544
#define PCHUNKS 16
#define PSZ    (NB * NT * NRANK)   // 32768
#define KSPLIT 8

// ---- final GEMM (cp.async fp16 x fp16, BK=64, 3 stages) ----
#define FBK    64
#define FNIT   (GK / FBK)    // 16
#define FSRA   144
#define FSRB   272
#define FATILE (128 * FSRA)  // 18432
#define FBTILE (64 * FSRB)   // 17408
#define FSTAGE (FATILE + FBTILE)   // 35840
#define FSMEM  (3 * FSTAGE)        // 107520

// ---------------- scratch ----------------------------------------------------
__device__ __half g_ae[NB * NADA];
__device__ __half g_h[NB * NINTER];
__device__ __half g_x16[NB * NT * ND];
__device__ __half g_base16[ND * ND];
__device__ float  g_hpart[KSPLIT * NB * NINTER];
__device__ float  g_xw[NB * 2 * ND * NRANK];
__device__ float  g_Ppart[PCHUNKS * PSZ];

// ---------------- PTX helpers -------------------------------------------------
__device__ __forceinline__ uint32_t smem_u32(const void* p) {
    uint32_t a;
    asm("{ .reg .u64 t; cvta.to.shared.u64 t, %1; cvt.u32.u64 %0, t; }" : "=r"(a) : "l"(p));
    return a;
}
#define CP16(sa, ga) \
    asm volatile("cp.async.cg.shared.global [%0], [%1], 16;" :: "r"(sa), "l"(ga))
#define CP_COMMIT() asm volatile("cp.async.commit_group;")
#define CP_WAIT(n)  asm volatile("cp.async.wait_group %0;" :: "n"(n))
#define LDSM4(r, addr) \
    asm volatile("ldmatrix.sync.aligned.m8n8.x4.shared.b16 {%0,%1,%2,%3}, [%4];" \
        : "=r"((r)[0]), "=r"((r)[1]), "=r"((r)[2]), "=r"((r)[3]) : "r"(addr))
#define LDSM4T(r, addr) \
    asm volatile("ldmatrix.sync.aligned.m8n8.x4.trans.shared.b16 {%0,%1,%2,%3}, [%4];" \
        : "=r"((r)[0]), "=r"((r)[1]), "=r"((r)[2]), "=r"((r)[3]) : "r"(addr))
#define MMA_F16(d, a, b0, b1) \
    asm volatile("mma.sync.aligned.m16n8k16.row.col.f32.f16.f16.f32 " \
        "{%0,%1,%2,%3},{%4,%5,%6,%7},{%8,%9},{%0,%1,%2,%3};" \
        : "+f"((d)[0]), "+f"((d)[1]), "+f"((d)[2]), "+f"((d)[3]) \
        : "r"((a)[0]), "r"((a)[1]), "r"((a)[2]), "r"((a)[3]), "r"(b0), "r"(b1))

__device__ __forceinline__ float gelu_exact(float v) {
    return 0.5f * v * (1.0f + erff(v * 0.70710678118654752f));
}

// ---------------- fused fp32 -> fp16 conversion (x and base) ------------------
__global__ __launch_bounds__(256) void cvt16_dual_kernel(
    const float4* __restrict__ srcx, __half* __restrict__ dstx, int n4x,
    const float4* __restrict__ srcb, __half* __restrict__ dstb, int n4tot)
{
    int i = blockIdx.x * 256 + threadIdx.x;
    if (i >= n4tot) return;
    const float4* s; __half* d; int j;
    if (i < n4x) { s = srcx; d = dstx; j = i; }
    else         { s = srcb; d = dstb; j = i - n4x; }
    float4 v = s[j];
    __half2 hh[2] = { __floats2half2_rn(v.x, v.y), __floats2half2_rn(v.z, v.w) };
    *reinterpret_cast<uint2*>(d + (size_t)j * 4) = *reinterpret_cast<uint2*>(hh);
}

// ---------------- layernorm (writes fp16) -------------------------------------
__global__ __launch_bounds__(256) void layernorm_kernel(
    const float* __restrict__ ada, const float* __restrict__ gamma,
    const float* __restrict__ beta, __half* __restrict__ outh)
{
    int row = blockIdx.x;
    const float4 v = reinterpret_cast<const float4*>(ada + (size_t)row * NADA)[threadIdx.x];
    float s  = v.x + v.y + v.z + v.w;
    float ss = v.x * v.x + v.y * v.y + v.z * v.z + v.w * v.w;
    __shared__ float rs[8], rq[8];
    #pragma unroll
    for (int o = 16; o > 0; o >>= 1) {
        s  += __shfl_xor_sync(0xFFFFFFFFu, s, o);
        ss += __shfl_xor_sync(0xFFFFFFFFu, ss, o);
    }
    int warp = threadIdx.x >> 5, lane = threadIdx.x & 31;
    if (lane == 0) { rs[warp] = s; rq[warp] = ss; }
    __syncthreads();
    float sum = 0.f, sumsq = 0.f;
    #pragma unroll
    for (int i = 0; i < 8; i++) { sum += rs[i]; sumsq += rq[i]; }
    const float inv_n = 1.0f / NADA;
    float mu = sum * inv_n;
    float rstd = rsqrtf(sumsq * inv_n - mu * mu + 1e-5f);
    const float4 gv = reinterpret_cast<const float4*>(gamma)[threadIdx.x];
    const float4 bv = reinterpret_cast<const float4*>(beta)[threadIdx.x];
    float o0 = (v.x - mu) * rstd * gv.x + bv.x;
    float o1 = (v.y - mu) * rstd * gv.y + bv.y;
    float o2 = (v.z - mu) * rstd * gv.z + bv.z;
    float o3 = (v.w - mu) * rstd * gv.w + bv.w;
    __half2 hh[2] = { __floats2half2_rn(o0, o1), __floats2half2_rn(o2, o3) };
    *reinterpret_cast<uint2*>(outh + (size_t)row * NADA + threadIdx.x * 4) =
        *reinterpret_cast<uint2*>(hh);
}

// ---------------- reduce split-K partials + bias + GELU -> fp16 ---------------
__global__ __launch_bounds__(256) void reduce_gelu_kernel(
    const float* __restrict__ part, const float* __restrict__ b1,
    __half* __restrict__ h)
{
    int i = blockIdx.x * 256 + threadIdx.x;
    const float4* p = reinterpret_cast<const float4*>(part);
    float4 s = p[i];
    #pragma unroll
    for (int z = 1; z < KSPLIT; z++) {
        float4 t = p[(size_t)z * (NB * NINTER / 4) + i];
        s.x += t.x; s.y += t.y; s.z += t.z; s.w += t.w;
    }
    const float4 bb = reinterpret_cast<const float4*>(b1)[i & (NINTER / 4 - 1)];
    float g0 = gelu_exact(s.x + bb.x), g1 = gelu_exact(s.y + bb.y);
    float g2 = gelu_exact(s.z + bb.z), g3 = gelu_exact(s.w + bb.w);
    __half2 hh[2] = { __floats2half2_rn(g0, g1), __floats2half2_rn(g2, g3) };
    *reinterpret_cast<uint2*>(h + (size_t)i * 4) = *reinterpret_cast<uint2*>(hh);
}

// ---------------- partial P ----------------------------------------------------
__global__ __launch_bounds__(256) void p_partial_kernel(
    const __half* __restrict__ x16, const float* __restrict__ xw, float* __restrict__ Pp)
{
    int b = blockIdx.x, cch = blockIdx.y;
    int w = threadIdx.x >> 5, lane = threadIdx.x & 31;
    const float* xa = xw + (size_t)b * (2 * ND * NRANK) + cch * 64 * NRANK;
    #pragma unroll
    for (int t = w; t < NT; t += 8) {
        const __half* xrow = x16 + ((size_t)b * NT + t) * ND + cch * 64;
        float acc[8] = {0, 0, 0, 0, 0, 0, 0, 0};
        #pragma unroll
        for (int ds = 0; ds < 2; ds++) {
            int d = ds * 32 + lane;
            float xv = __half2float(xrow[d]);
            float4 a0 = *reinterpret_cast<const float4*>(xa + d * 8);
            float4 a1 = *reinterpret_cast<const float4*>(xa + d * 8 + 4);
            acc[0] += xv * a0.x; acc[1] += xv * a0.y;
            acc[2] += xv * a0.z; acc[3] += xv * a0.w;
            acc[4] += xv * a1.x; acc[5] += xv * a1.y;
            acc[6] += xv * a1.z; acc[7] += xv * a1.w;
        }
        #pragma unroll
        for (int r = 0; r < 8; r++) {
            float sv = acc[r];
            #pragma unroll
            for (int o = 16; o > 0; o >>= 1) sv += __shfl_xor_sync(0xFFFFFFFFu, sv, o);
            if (lane == r) Pp[(size_t)cch * PSZ + ((size_t)b * NT + t) * NRANK + r] = sv;
        }
    }
}

// ---------------- pipelined GEMM, A fp16 + B fp32 (cvt in fragment load) ------
// 4 stages, lookahead 3: compute reads buf c%4, issue writes (c+3)%4 — no overlap.
// MODE 0: split-K raw fp32 partials (z = blockIdx.z), no bias
// MODE 1: +bias -> fp32
template<int MODE, int NIT>
__global__ __launch_bounds__(256) void pipe_gemm32_kernel(
    const __half* __restrict__ A, const float* __restrict__ B, int N,
    const float* __restrict__ bias, float* __restrict__ outf)
{
    extern __shared__ char smem[];
    const int tid = threadIdx.x, wid = tid >> 5, lane = tid & 31;
    const int m0 = blockIdx.y * BM, n0 = blockIdx.x * BN;
    const int kb = (MODE == 0) ? blockIdx.z * (NIT * BK) : 0;
    const int wm = wid & 1, wn = wid >> 1;
    const uint32_t sb = smem_u32(smem);

    float acc[4][4][4];
    #pragma unroll
    for (int i = 0; i < 4; i++)
        #pragma unroll
        for (int j = 0; j < 4; j++)
            #pragma unroll
            for (int e = 0; e < 4; e++) acc[i][j][e] = 0.f;

    auto issue = [&](int c) {
        uint32_t st = sb + (c % NSTG) * STG32;
        int k0 = kb + c * BK;
        #pragma unroll
        for (int i = 0; i < 2; i++) {          // A: 128 rows x 64B fp16
            int ch = tid + i * 256, r = ch >> 2, cc = ch & 3;
            CP16(st + r * SRA + cc * 16, A + (size_t)(m0 + r) * GK + k0 + cc * 8);
        }
        #pragma unroll
        for (int i = 0; i < 4; i++) {          // B: 32 rows x 512B fp32
            int ch = tid + i * 256, r = ch >> 5, cc = ch & 31;
            CP16(st + ATILE + r * SRB32 + cc * 16, B + (size_t)(k0 + r) * N + n0 + cc * 4);
        }
        CP_COMMIT();
    };

    const int a_row = wm * 64 + (lane & 15);
    const int a_off = (lane >> 4) * 16;
    const int b_n   = lane >> 2;               // 0..7 within 8-col tile
    const int b_kp  = (lane & 3) * 2;          // 0,2,4,6

    issue(0);
    if (NIT > 1) issue(1);
    if (NIT > 2) issue(2);

    for (int c = 0; c < NIT; c++) {
        int rem = NIT - 1 - c;
        if (rem >= 2) CP_WAIT(2); else if (rem == 1) CP_WAIT(1); else CP_WAIT(0);
        __syncthreads();
        if (c + 3 < NIT) issue(c + 3);

        const char* bstg = smem + ((c % NSTG) * STG32) + ATILE;
        uint32_t abase = sb + (c % NSTG) * STG32;
        #pragma unroll
        for (int ks = 0; ks < 2; ks++) {
            uint32_t af[4][4];
            #pragma unroll
            for (int mt = 0; mt < 4; mt++)
                LDSM4(af[mt], abase + (a_row + mt * 16) * SRA + ks * 32 + a_off);
            #pragma unroll
            for (int nt = 0; nt < 4; nt++) {
                int ncol = wn * 32 + nt * 8 + b_n;
                const char* col = bstg + (size_t)ncol * 4;
                int r0 = ks * 16 + b_kp;
                float f0 = *reinterpret_cast<const float*>(col + (r0 + 0) * SRB32);
                float f1 = *reinterpret_cast<const float*>(col + (r0 + 1) * SRB32);
                float f2 = *reinterpret_cast<const float*>(col + (r0 + 8) * SRB32);
                float f3 = *reinterpret_cast<const float*>(col + (r0 + 9) * SRB32);
                __half2 h01 = __floats2half2_rn(f0, f1);
                __half2 h23 = __floats2half2_rn(f2, f3);
                uint32_t b0 = *reinterpret_cast<uint32_t*>(&h01);
                uint32_t b1 = *reinterpret_cast<uint32_t*>(&h23);
                #pragma unroll
                for (int mt = 0; mt < 4; mt++)
                    MMA_F16(acc[mt][nt], af[mt], b0, b1);
            }
        }
    }

    float* po = outf;
    if (MODE == 0) po += (size_t)blockIdx.z * (NB * NINTER);
    #pragma unroll
    for (int mt = 0; mt < 4; mt++) {
        int r_in0 = wm * 64 + mt * 16 + (lane >> 2);
        #pragma unroll
        for (int half = 0; half < 2; half++) {
            int m = m0 + r_in0 + half * 8;
            #pragma unroll
            for (int nt = 0; nt < 4; nt++) {
                int n = n0 + wn * 32 + nt * 8 + (lane & 3) * 2;
                float v0 = acc[mt][nt][half * 2 + 0];
                float v1 = acc[mt][nt][half * 2 + 1];
                if (MODE == 1) { v0 += bias[n]; v1 += bias[n + 1]; }
                float2 o; o.x = v0; o.y = v1;
                *reinterpret_cast<float2*>(po + (size_t)m * N + n) = o;
            }
        }
    }
}

// ---------------- final GEMM: cp.async 3-stage, BK=64, fp16 x fp16 ------------
__global__ __launch_bounds__(256, 2) void gemm_final_kernel(
    const __half* __restrict__ A, const __half* __restrict__ B,
    float* __restrict__ outf, const float* __restrict__ xres,
    const float* __restrict__ Pp, const float* __restrict__ xw)
{
    extern __shared__ char smem[];
    const int tid = threadIdx.x, wid = tid >> 5, lane = tid & 31;
    const int m0 = blockIdx.y * BM, n0 = blockIdx.x * BN;
    const int wm = wid & 1, wn = wid >> 1;
    const uint32_t sb = smem_u32(smem);
    const int N = ND;

    float acc[4][4][4];
    #pragma unroll
    for (int i = 0; i < 4; i++)
        #pragma unroll
        for (int j = 0; j < 4; j++)
            #pragma unroll
            for (int e = 0; e < 4; e++) acc[i][j][e] = 0.f;

    auto issue = [&](int c) {
        uint32_t st = sb + (c % 3) * FSTAGE;
        int k0 = c * FBK;
        #pragma unroll
        for (int i = 0; i < 4; i++) {
            int ch = tid + i * 256, r = ch >> 3, cc = ch & 7;
            CP16(st + r * FSRA + cc * 16, A + (size_t)(m0 + r) * GK + k0 + cc * 8);
        }
        #pragma unroll
        for (int i = 0; i < 4; i++) {
            int ch = tid + i * 256, r = ch >> 4, cc = ch & 15;
            CP16(st + FATILE + r * FSRB + cc * 16, B + (size_t)(k0 + r) * N + n0 + cc * 8);
        }
        CP_COMMIT();
    };

    const int a_row  = wm * 64 + (lane & 15);
    const int a_off  = (lane >> 4) * 16;
    const int b_row  = lane & 15;
    const int b_colb = wn * 64 + (lane >> 4) * 16;

    issue(0);
    issue(1);

    for (int c = 0; c < FNIT; c++) {
        if (c < FNIT - 1) CP_WAIT(1); else CP_WAIT(0);
        __syncthreads();
        if (c + 2 < FNIT) issue(c + 2);

        uint32_t base = sb + (c % 3) * FSTAGE;
        #pragma unroll
        for (int ks = 0; ks < 4; ks++) {
            uint32_t af[4][4];
            #pragma unroll
            for (int mt = 0; mt < 4; mt++)
                LDSM4(af[mt], base + (a_row + mt * 16) * FSRA + ks * 32 + a_off);
            uint32_t bf[4][2];
            #pragma unroll
            for (int pr = 0; pr < 2; pr++) {
                uint32_t r[4];
                LDSM4T(r, base + FATILE + (ks * 16 + b_row) * FSRB + b_colb + pr * 32);
                bf[pr * 2 + 0][0] = r[0]; bf[pr * 2 + 0][1] = r[1];
                bf[pr * 2 + 1][0] = r[2]; bf[pr * 2 + 1][1] = r[3];
            }
            #pragma unroll
            for (int mt = 0; mt < 4; mt++)
                #pragma unroll
                for (int nt = 0; nt < 4; nt++)
                    MMA_F16(acc[mt][nt], af[mt], bf[nt][0], bf[nt][1]);
        }
    }
    __syncthreads();

    // epilogue: + xres + P @ x_b^T
    float* Ps  = reinterpret_cast<float*>(smem);
    float* xbs = reinterpret_cast<float*>(smem + 4096);
    for (int i = tid; i < BM * NRANK; i += 256) {
        float sv = 0.f;
        #pragma unroll
        for (int c = 0; c < PCHUNKS; c++)
            sv += Pp[(size_t)c * PSZ + (size_t)m0 * NRANK + i];
        Ps[i] = sv;
    }
    for (int i = tid; i < 4 * BN * NRANK; i += 256) {
        int g = i >> 10, j = (i >> 3) & 127, r = i & 7;
        int bg = (m0 >> 5) + g;
        xbs[i] = xw[(size_t)bg * (2 * ND * NRANK) + ND * NRANK + (size_t)(n0 + j) * NRANK + r];
    }
    __syncthreads();

    #pragma unroll
    for (int mt = 0; mt < 4; mt++) {
        int r_in0 = wm * 64 + mt * 16 + (lane >> 2);
        #pragma unroll
        for (int half = 0; half < 2; half++) {
            int r_in = r_in0 + half * 8;
            int m = m0 + r_in;
            int g = r_in >> 5;
            const float4* pr = reinterpret_cast<const float4*>(Ps + r_in * 8);
            float4 p0 = pr[0], p1 = pr[1];
            #pragma unroll
            for (int nt = 0; nt < 4; nt++) {
                int c_in = wn * 32 + nt * 8 + (lane & 3) * 2;
                int n = n0 + c_in;
                const float4* xb0 = reinterpret_cast<const float4*>(xbs + (g * 128 + c_in) * 8);
                const float4* xb1 = reinterpret_cast<const float4*>(xbs + (g * 128 + c_in + 1) * 8);
                float4 u0 = xb0[0], u1 = xb0[1], v0 = xb1[0], v1 = xb1[1];
                float e0 = p0.x * u0.x + p0.y * u0.y + p0.z * u0.z + p0.w * u0.w
                         + p1.x * u1.x + p1.y * u1.y + p1.z * u1.z + p1.w * u1.w;
                float e1 = p0.x * v0.x + p0.y * v0.y + p0.z * v0.z + p0.w * v0.w
                         + p1.x * v1.x + p1.y * v1.y + p1.z * v1.z + p1.w * v1.w;
                const float2 xr = *reinterpret_cast<const float2*>(xres + (size_t)m * N + n);
                float2 o;
                o.x = xr.x + acc[mt][nt][half * 2 + 0] + e0;
                o.y = xr.y + acc[mt][nt][half * 2 + 1] + e1;
                *reinterpret_cast<float2*>(outf + (size_t)m * N + n) = o;
            }
        }
    }
}

// ---------------------------------------------------------------------------
extern "C" void kernel_launch(void* const* d_in, const int* in_sizes, int n_in,
                              void* d_out, int out_size)
{
    const float* x    = (const float*)d_in[0];
    const float* ada  = (const float*)d_in[1];
    const float* base = (const float*)d_in[2];
    const float* w1   = (const float*)d_in[3];
    const float* b1   = (const float*)d_in[4];
    const float* w2   = (const float*)d_in[5];
    const float* b2   = (const float*)d_in[6];
    const float* ln_g = (const float*)d_in[7];
    const float* ln_b = (const float*)d_in[8];
    float* out = (float*)d_out;

    __half *ae, *h, *x16, *base16;
    float *xw, *Pp, *hpart;
    cudaGetSymbolAddress((void**)&ae, g_ae);
    cudaGetSymbolAddress((void**)&h,  g_h);
    cudaGetSymbolAddress((void**)&x16, g_x16);
    cudaGetSymbolAddress((void**)&base16, g_base16);
    cudaGetSymbolAddress((void**)&hpart, g_hpart);
    cudaGetSymbolAddress((void**)&xw, g_xw);
    cudaGetSymbolAddress((void**)&Pp, g_Ppart);

    cudaFuncSetAttribute((const void*)pipe_gemm32_kernel<0, 4>,
                         cudaFuncAttributeMaxDynamicSharedMemorySize, SMEM32);
    cudaFuncSetAttribute((const void*)pipe_gemm32_kernel<1, 32>,
                         cudaFuncAttributeMaxDynamicSharedMemorySize, SMEM32);
    cudaFuncSetAttribute((const void*)gemm_final_kernel,
                         cudaFuncAttributeMaxDynamicSharedMemorySize, FSMEM);

    // one-time fp16 conversions (fused)
    int n4x = NB * NT * ND / 4, n4b = ND * ND / 4;
    cvt16_dual_kernel<<<(n4x + n4b + 255) / 256, 256>>>(
        (const float4*)x, x16, n4x, (const float4*)base, base16, n4x + n4b);

    // hypernetwork
    layernorm_kernel<<<NB, 256>>>(ada, ln_g, ln_b, ae);
    pipe_gemm32_kernel<0, 4><<<dim3(NINTER / BN, 1, KSPLIT), 256, SMEM32>>>(
        ae, w1, NINTER, nullptr, hpart);
    reduce_gelu_kernel<<<NB * NINTER / 4 / 256, 256>>>(hpart, b1, h);
    pipe_gemm32_kernel<1, 32><<<dim3(2 * ND * NRANK / BN, 1), 256, SMEM32>>>(
        h, w2, 2 * ND * NRANK, b2, xw);

    // low-rank path + fused final GEMM
    p_partial_kernel<<<dim3(NB, PCHUNKS), 256>>>(x16, xw, Pp);
    gemm_final_kernel<<<dim3(ND / BN, NB * NT / BM), 256, FSMEM>>>(
        x16, base16, out, x, Pp, xw);
}